// round 5
// baseline (speedup 1.0000x reference)
#include <cuda_runtime.h>
#include <math.h>
#include <cstdint>

#define TOK   4096          // B*S
#define SEQ   2048
#define EMB   1024
#define NHEAD 16
#define HDIM  64
#define FFD   4096

// -------- scratch ----
__device__ float g_h  [TOK * EMB];
__device__ float g_q  [TOK * EMB];
__device__ float g_k  [TOK * EMB];
__device__ float g_v  [TOK * EMB];
__device__ float g_at [TOK * EMB];
__device__ float g_x1 [TOK * EMB];
__device__ float g_h2 [TOK * EMB];
__device__ float g_ff [TOK * FFD];
// tf32-rounded weights
__device__ float g_wq [EMB * EMB];
__device__ float g_wk [EMB * EMB];
__device__ float g_wv [EMB * EMB];
__device__ float g_wo [EMB * EMB];
__device__ float g_w1 [EMB * FFD];
__device__ float g_w2 [FFD * EMB];

// --------------------------- helpers ------------------------------------------
__device__ __forceinline__ float to_tf32(float x) {
    float r;
    asm("cvt.rna.tf32.f32 %0, %1;" : "=f"(r) : "f"(x));
    return r;
}
__device__ __forceinline__ float4 cvt4(float4 v) {
    return make_float4(to_tf32(v.x), to_tf32(v.y), to_tf32(v.z), to_tf32(v.w));
}
__device__ __forceinline__ uint32_t smem_u32(const void* p) {
    uint32_t a;
    asm("{ .reg .u64 t; cvta.to.shared.u64 t, %1; cvt.u32.u64 %0, t; }" : "=r"(a) : "l"(p));
    return a;
}
__device__ __forceinline__ void cp_async16(uint32_t dst, const void* src) {
    asm volatile("cp.async.cg.shared.global [%0], [%1], 16;" :: "r"(dst), "l"(src));
}
__device__ __forceinline__ void cp_commit() {
    asm volatile("cp.async.commit_group;" ::: "memory");
}
__device__ __forceinline__ void cp_wait1() {
    asm volatile("cp.async.wait_group 1;" ::: "memory");
}
__device__ __forceinline__ void mma_tf32(float* d, const float* a, const float* b) {
    asm volatile(
        "mma.sync.aligned.m16n8k8.row.col.f32.tf32.tf32.f32 "
        "{%0,%1,%2,%3},{%4,%5,%6,%7},{%8,%9},{%0,%1,%2,%3};"
        : "+f"(d[0]), "+f"(d[1]), "+f"(d[2]), "+f"(d[3])
        : "r"(__float_as_uint(a[0])), "r"(__float_as_uint(a[1])),
          "r"(__float_as_uint(a[2])), "r"(__float_as_uint(a[3])),
          "r"(__float_as_uint(b[0])), "r"(__float_as_uint(b[1])));
}

// ------------------------- weight tf32 conversion -----------------------------
// 12M floats total -> 3M float4, grid-strided
__global__ void cvt_weights(const float* __restrict__ wq, const float* __restrict__ wk,
                            const float* __restrict__ wv, const float* __restrict__ wo,
                            const float* __restrict__ w1, const float* __restrict__ w2) {
    const int Q1 = EMB * EMB / 4;            // 256K float4 per EMBxEMB
    int i = blockIdx.x * blockDim.x + threadIdx.x;   // 0 .. 3M-1
    const float4* src;
    float4* dst;
    int off;
    if (i < Q1)            { src = (const float4*)wq; dst = (float4*)g_wq; off = i; }
    else if (i < 2 * Q1)   { src = (const float4*)wk; dst = (float4*)g_wk; off = i - Q1; }
    else if (i < 3 * Q1)   { src = (const float4*)wv; dst = (float4*)g_wv; off = i - 2 * Q1; }
    else if (i < 4 * Q1)   { src = (const float4*)wo; dst = (float4*)g_wo; off = i - 3 * Q1; }
    else if (i < 8 * Q1)   { src = (const float4*)w1; dst = (float4*)g_w1; off = i - 4 * Q1; }
    else                   { src = (const float4*)w2; dst = (float4*)g_w2; off = i - 8 * Q1; }
    dst[off] = cvt4(src[off]);
}

// ------------------------------- LayerNorm (tf32-rounded out) -----------------
__global__ void ln_kernel(const float* __restrict__ x, const float* __restrict__ g,
                          const float* __restrict__ b, float* __restrict__ out) {
    int t = blockIdx.x;
    int tid = threadIdx.x;
    const float* row = x + (size_t)t * EMB;
    float vals[4];
    float sum = 0.f, sq = 0.f;
#pragma unroll
    for (int it = 0; it < 4; it++) {
        float v = row[tid + it * 256];
        vals[it] = v; sum += v; sq += v * v;
    }
    __shared__ float s1[256], s2[256];
    s1[tid] = sum; s2[tid] = sq;
    __syncthreads();
    for (int st = 128; st > 0; st >>= 1) {
        if (tid < st) { s1[tid] += s1[tid + st]; s2[tid] += s2[tid + st]; }
        __syncthreads();
    }
    float mu   = s1[0] * (1.f / EMB);
    float var  = s2[0] * (1.f / EMB) - mu * mu;
    float rstd = rsqrtf(var + 1e-5f);
#pragma unroll
    for (int it = 0; it < 4; it++) {
        int i = tid + it * 256;
        out[(size_t)t * EMB + i] = to_tf32((vals[it] - mu) * rstd * g[i] + b[i]);
    }
}

// --------------------- tf32 mma GEMM, cp.async 3-stage, BK=32 -----------------
// A, W must be pre-rounded to tf32. 128x128 tile, 256 threads, 8 warps (2x4),
// warp tile 64x32. As stride 36 floats (144B), Bs stride 136 floats (544B).
#define AST   36
#define BST   136
#define ABYTES (128 * AST * 4)     // 18432
#define BBYTES (32 * BST * 4)      // 17408
#define GSMEM  (3 * (ABYTES + BBYTES))   // 107520

template <int ACT, int ROUND>
__device__ __forceinline__
void gemm_core(const float* __restrict__ A, const float* __restrict__ W,
               const float* __restrict__ bias, const float* __restrict__ res,
               float* __restrict__ C, int M, int N, int K, int m0, int n0,
               char* smem) {
    uint32_t sbase = smem_u32(smem);
    int tid  = threadIdx.x;
    int lane = tid & 31, warp = tid >> 5;
    int g = lane >> 2, t = lane & 3;
    int wm = (warp >> 2) * 64;
    int wn = (warp & 3) * 32;

    // cp.async mappings
    int a_row = tid >> 1;                 // 0..127
    int a_cb  = (tid & 1) * 16;           // float col base (2 thr/row, 64B each)
    int b_row = tid >> 3;                 // 0..31 (k)
    int b_cb  = (tid & 7) * 16;           // float col base

    const float* Ap = A + (size_t)(m0 + a_row) * K + a_cb;
    const float* Wp = W + (size_t)b_row * N + n0 + b_cb;
    uint32_t a_dst0 = sbase + a_row * (AST * 4) + a_cb * 4;
    uint32_t b_dst0 = sbase + 3 * ABYTES + b_row * (BST * 4) + b_cb * 4;

    int nkb = K >> 5;

#define ISSUE(kb, s)                                                           \
    do {                                                                       \
        const float* asrc = Ap + (kb) * 32;                                    \
        const float* bsrc = Wp + (size_t)(kb) * 32 * N;                        \
        uint32_t ad = a_dst0 + (s) * ABYTES;                                   \
        uint32_t bd = b_dst0 + (s) * BBYTES;                                   \
        cp_async16(ad,      asrc);      cp_async16(ad + 16, asrc + 4);         \
        cp_async16(ad + 32, asrc + 8);  cp_async16(ad + 48, asrc + 12);        \
        cp_async16(bd,      bsrc);      cp_async16(bd + 16, bsrc + 4);         \
        cp_async16(bd + 32, bsrc + 8);  cp_async16(bd + 48, bsrc + 12);        \
    } while (0)

    ISSUE(0, 0); cp_commit();
    if (nkb > 1) ISSUE(1, 1);
    cp_commit();

    float acc[4][4][4] = {};

    for (int kb = 0; kb < nkb; kb++) {
        cp_wait1();
        __syncthreads();

        int buf = kb % 3;
        const float* As = (const float*)(smem + buf * ABYTES);
        const float* Bs = (const float*)(smem + 3 * ABYTES + buf * BBYTES);

#pragma unroll
        for (int kk = 0; kk < 4; kk++) {
            float a[4][4], b[4][2];
#pragma unroll
            for (int mf = 0; mf < 4; mf++) {
                int r = wm + mf * 16;
                a[mf][0] = As[(r + g)     * AST + kk * 8 + t];
                a[mf][1] = As[(r + g + 8) * AST + kk * 8 + t];
                a[mf][2] = As[(r + g)     * AST + kk * 8 + t + 4];
                a[mf][3] = As[(r + g + 8) * AST + kk * 8 + t + 4];
            }
#pragma unroll
            for (int nf = 0; nf < 4; nf++) {
                int c = wn + nf * 8 + g;
                b[nf][0] = Bs[(kk * 8 + t)     * BST + c];
                b[nf][1] = Bs[(kk * 8 + t + 4) * BST + c];
            }
#pragma unroll
            for (int mf = 0; mf < 4; mf++)
#pragma unroll
                for (int nf = 0; nf < 4; nf++)
                    mma_tf32(acc[mf][nf], a[mf], b[nf]);
        }

        __syncthreads();
        if (kb + 2 < nkb) ISSUE(kb + 2, (kb + 2) % 3);
        cp_commit();
    }
#undef ISSUE

    // epilogue
#pragma unroll
    for (int mf = 0; mf < 4; mf++) {
#pragma unroll
        for (int nf = 0; nf < 4; nf++) {
            int mA = m0 + wm + mf * 16 + g;
            int mB = mA + 8;
            int n_ = n0 + wn + nf * 8 + 2 * t;
            float bn0 = bias[n_], bn1 = bias[n_ + 1];

            float v00 = acc[mf][nf][0] + bn0;
            float v01 = acc[mf][nf][1] + bn1;
            float v10 = acc[mf][nf][2] + bn0;
            float v11 = acc[mf][nf][3] + bn1;
            if (res) {
                const float2 r0 = *(const float2*)(res + (size_t)mA * N + n_);
                const float2 r1 = *(const float2*)(res + (size_t)mB * N + n_);
                v00 += r0.x; v01 += r0.y; v10 += r1.x; v11 += r1.y;
            }
            if (ACT == 1) {
                v00 = 0.5f * v00 * (1.f + erff(v00 * 0.70710678118654752f));
                v01 = 0.5f * v01 * (1.f + erff(v01 * 0.70710678118654752f));
                v10 = 0.5f * v10 * (1.f + erff(v10 * 0.70710678118654752f));
                v11 = 0.5f * v11 * (1.f + erff(v11 * 0.70710678118654752f));
            }
            if (ROUND == 1) {
                v00 = to_tf32(v00); v01 = to_tf32(v01);
                v10 = to_tf32(v10); v11 = to_tf32(v11);
            }
            *(float2*)(C + (size_t)mA * N + n_) = make_float2(v00, v01);
            *(float2*)(C + (size_t)mB * N + n_) = make_float2(v10, v11);
        }
    }
}

template <int ACT, int ROUND>
__global__ __launch_bounds__(256)
void tf32_gemm(const float* __restrict__ A, const float* __restrict__ W,
               const float* __restrict__ bias, const float* __restrict__ res,
               float* __restrict__ C, int M, int N, int K) {
    extern __shared__ char smem[];
    gemm_core<ACT, ROUND>(A, W, bias, res, C, M, N, K,
                          blockIdx.y * 128, blockIdx.x * 128, smem);
}

// fused QKV: gridDim.x = 24 (3 weights x 8 n-blocks)
__global__ __launch_bounds__(256)
void qkv_gemm(const float* __restrict__ A,
              const float* __restrict__ bq, const float* __restrict__ bk,
              const float* __restrict__ bv,
              float* __restrict__ Qo, float* __restrict__ Ko, float* __restrict__ Vo) {
    extern __shared__ char smem[];
    int wsel = blockIdx.x >> 3;
    int n0   = (blockIdx.x & 7) * 128;
    const float* W;
    const float* bias;
    float* C;
    if (wsel == 0)      { W = g_wq; bias = bq; C = Qo; }
    else if (wsel == 1) { W = g_wk; bias = bk; C = Ko; }
    else                { W = g_wv; bias = bv; C = Vo; }
    gemm_core<0, 0>(A, W, bias, nullptr, C, TOK, EMB, EMB,
                    blockIdx.y * 128, n0, smem);
}

// -------------------- Tensor-core flash attention (tf32) ----------------------
#define KST 68
#define VST 72
#define SST 68

__global__ __launch_bounds__(128)
void attn_tc(const float* __restrict__ Q, const float* __restrict__ K,
             const float* __restrict__ V, float* __restrict__ O) {
    extern __shared__ float sm[];
    float* Ks = sm;
    float* Vs = Ks + 64 * KST;
    float* Ss = Vs + 64 * VST;

    int qt = (int)gridDim.x - 1 - (int)blockIdx.x;
    int bh = blockIdx.y;
    int bb = bh >> 4, hh = bh & 15;
    int tid  = threadIdx.x;
    int warp = tid >> 5, lane = tid & 31;
    int g = lane >> 2, t = lane & 3;
    int r0 = warp * 16;

    size_t base = (size_t)bb * SEQ * EMB + (size_t)hh * HDIM;

#pragma unroll
    for (int it = 0; it < 8; it++) {
        int r = (tid >> 4) + it * 8;
        int c = (tid & 15) * 4;
        float4 v = *(const float4*)(Q + base + (size_t)(qt * 64 + r) * EMB + c);
        float4 w = make_float4(to_tf32(v.x * 0.125f), to_tf32(v.y * 0.125f),
                               to_tf32(v.z * 0.125f), to_tf32(v.w * 0.125f));
        *(float4*)&Ss[r * SST + c] = w;
    }
    __syncthreads();

    float qf[8][4];
#pragma unroll
    for (int kc = 0; kc < 8; kc++) {
        qf[kc][0] = Ss[(r0 + g)     * SST + kc * 8 + t];
        qf[kc][1] = Ss[(r0 + g + 8) * SST + kc * 8 + t];
        qf[kc][2] = Ss[(r0 + g)     * SST + kc * 8 + t + 4];
        qf[kc][3] = Ss[(r0 + g + 8) * SST + kc * 8 + t + 4];
    }

    float o[8][4] = {};
    float m0 = -1e30f, m1 = -1e30f, l0 = 0.f, l1 = 0.f;

    for (int kt = 0; kt <= qt; kt++) {
#pragma unroll
        for (int it = 0; it < 8; it++) {
            int r = (tid >> 4) + it * 8;
            int c = (tid & 15) * 4;
            size_t go = base + (size_t)(kt * 64 + r) * EMB + c;
            float4 kv = *(const float4*)(K + go);
            float4 vv = *(const float4*)(V + go);
            *(float4*)&Ks[r * KST + c] = cvt4(kv);
            *(float4*)&Vs[r * VST + c] = cvt4(vv);
        }
        __syncthreads();

        float s[8][4];
#pragma unroll
        for (int nf = 0; nf < 8; nf++) {
            s[nf][0] = s[nf][1] = s[nf][2] = s[nf][3] = 0.f;
            const float* kr = &Ks[(nf * 8 + g) * KST];
#pragma unroll
            for (int kc = 0; kc < 8; kc++) {
                float b[2] = { kr[kc * 8 + t], kr[kc * 8 + t + 4] };
                mma_tf32(s[nf], qf[kc], b);
            }
        }

        if (kt == qt) {
            int rowA = r0 + g, rowB = r0 + g + 8;
#pragma unroll
            for (int nf = 0; nf < 8; nf++) {
                int c0 = nf * 8 + 2 * t, c1 = c0 + 1;
                if (c0 > rowA) s[nf][0] = -1e30f;
                if (c1 > rowA) s[nf][1] = -1e30f;
                if (c0 > rowB) s[nf][2] = -1e30f;
                if (c1 > rowB) s[nf][3] = -1e30f;
            }
        }

        float mx0 = -1e30f, mx1 = -1e30f;
#pragma unroll
        for (int nf = 0; nf < 8; nf++) {
            mx0 = fmaxf(mx0, fmaxf(s[nf][0], s[nf][1]));
            mx1 = fmaxf(mx1, fmaxf(s[nf][2], s[nf][3]));
        }
        mx0 = fmaxf(mx0, __shfl_xor_sync(0xffffffffu, mx0, 1));
        mx0 = fmaxf(mx0, __shfl_xor_sync(0xffffffffu, mx0, 2));
        mx1 = fmaxf(mx1, __shfl_xor_sync(0xffffffffu, mx1, 1));
        mx1 = fmaxf(mx1, __shfl_xor_sync(0xffffffffu, mx1, 2));

        float m0n = fmaxf(m0, mx0), m1n = fmaxf(m1, mx1);
        float rs0 = __expf(m0 - m0n), rs1 = __expf(m1 - m1n);
        m0 = m0n; m1 = m1n;

        float sum0 = 0.f, sum1 = 0.f;
#pragma unroll
        for (int nf = 0; nf < 8; nf++) {
            s[nf][0] = __expf(s[nf][0] - m0);
            s[nf][1] = __expf(s[nf][1] - m0);
            s[nf][2] = __expf(s[nf][2] - m1);
            s[nf][3] = __expf(s[nf][3] - m1);
            sum0 += s[nf][0] + s[nf][1];
            sum1 += s[nf][2] + s[nf][3];
        }
        sum0 += __shfl_xor_sync(0xffffffffu, sum0, 1);
        sum0 += __shfl_xor_sync(0xffffffffu, sum0, 2);
        sum1 += __shfl_xor_sync(0xffffffffu, sum1, 1);
        sum1 += __shfl_xor_sync(0xffffffffu, sum1, 2);
        l0 = l0 * rs0 + sum0;
        l1 = l1 * rs1 + sum1;

        __syncwarp();
#pragma unroll
        for (int nf = 0; nf < 8; nf++) {
            int c = nf * 8 + 2 * t;
            *(float2*)&Ss[(r0 + g)     * SST + c] =
                make_float2(to_tf32(s[nf][0]), to_tf32(s[nf][1]));
            *(float2*)&Ss[(r0 + g + 8) * SST + c] =
                make_float2(to_tf32(s[nf][2]), to_tf32(s[nf][3]));
        }
        __syncwarp();

#pragma unroll
        for (int nf = 0; nf < 8; nf++) {
            o[nf][0] *= rs0; o[nf][1] *= rs0;
            o[nf][2] *= rs1; o[nf][3] *= rs1;
        }
#pragma unroll
        for (int kc = 0; kc < 8; kc++) {
            float pf[4];
            pf[0] = Ss[(r0 + g)     * SST + kc * 8 + t];
            pf[1] = Ss[(r0 + g + 8) * SST + kc * 8 + t];
            pf[2] = Ss[(r0 + g)     * SST + kc * 8 + t + 4];
            pf[3] = Ss[(r0 + g + 8) * SST + kc * 8 + t + 4];
            const float* v0 = &Vs[(kc * 8 + t)     * VST];
            const float* v1 = &Vs[(kc * 8 + t + 4) * VST];
#pragma unroll
            for (int nf = 0; nf < 8; nf++) {
                float b[2] = { v0[nf * 8 + g], v1[nf * 8 + g] };
                mma_tf32(o[nf], pf, b);
            }
        }
        __syncthreads();
    }

    // tf32-rounded output (feeds O-proj GEMM as A)
    float il0 = 1.f / l0, il1 = 1.f / l1;
    int rowA = qt * 64 + r0 + g;
    int rowB = rowA + 8;
#pragma unroll
    for (int nf = 0; nf < 8; nf++) {
        int c = nf * 8 + 2 * t;
        *(float2*)(O + base + (size_t)rowA * EMB + c) =
            make_float2(to_tf32(o[nf][0] * il0), to_tf32(o[nf][1] * il0));
        *(float2*)(O + base + (size_t)rowB * EMB + c) =
            make_float2(to_tf32(o[nf][2] * il1), to_tf32(o[nf][3] * il1));
    }
}

// ------------------------------- launch --------------------------------------
extern "C" void kernel_launch(void* const* d_in, const int* in_sizes, int n_in,
                              void* d_out, int out_size) {
    const float* x     = (const float*)d_in[0];
    const float* ln1_g = (const float*)d_in[2];
    const float* ln1_b = (const float*)d_in[3];
    const float* wq    = (const float*)d_in[4];
    const float* bq    = (const float*)d_in[5];
    const float* wk    = (const float*)d_in[6];
    const float* bk    = (const float*)d_in[7];
    const float* wv    = (const float*)d_in[8];
    const float* bv    = (const float*)d_in[9];
    const float* wo    = (const float*)d_in[10];
    const float* bo    = (const float*)d_in[11];
    const float* ln2_g = (const float*)d_in[12];
    const float* ln2_b = (const float*)d_in[13];
    const float* w1    = (const float*)d_in[14];
    const float* b1    = (const float*)d_in[15];
    const float* w2    = (const float*)d_in[16];
    const float* b2    = (const float*)d_in[17];
    float* out = (float*)d_out;

    float *h, *q, *k, *v, *at, *x1, *h2, *ff;
    float *dwq, *dwk, *dwv, *dwo, *dw1, *dw2;
    cudaGetSymbolAddress((void**)&h,  g_h);
    cudaGetSymbolAddress((void**)&q,  g_q);
    cudaGetSymbolAddress((void**)&k,  g_k);
    cudaGetSymbolAddress((void**)&v,  g_v);
    cudaGetSymbolAddress((void**)&at, g_at);
    cudaGetSymbolAddress((void**)&x1, g_x1);
    cudaGetSymbolAddress((void**)&h2, g_h2);
    cudaGetSymbolAddress((void**)&ff, g_ff);
    cudaGetSymbolAddress((void**)&dwq, g_wq);
    cudaGetSymbolAddress((void**)&dwk, g_wk);
    cudaGetSymbolAddress((void**)&dwv, g_wv);
    cudaGetSymbolAddress((void**)&dwo, g_wo);
    cudaGetSymbolAddress((void**)&dw1, g_w1);
    cudaGetSymbolAddress((void**)&dw2, g_w2);

    const int ATTN_SMEM = (64 * KST + 64 * VST + 64 * SST) * sizeof(float);
    cudaFuncSetAttribute(attn_tc, cudaFuncAttributeMaxDynamicSharedMemorySize, ATTN_SMEM);
    cudaFuncSetAttribute(tf32_gemm<0, 0>, cudaFuncAttributeMaxDynamicSharedMemorySize, GSMEM);
    cudaFuncSetAttribute(tf32_gemm<1, 1>, cudaFuncAttributeMaxDynamicSharedMemorySize, GSMEM);
    cudaFuncSetAttribute(qkv_gemm, cudaFuncAttributeMaxDynamicSharedMemorySize, GSMEM);

    // weights -> tf32 (12M floats = 3M float4)
    cvt_weights<<<(3 * EMB * EMB) / 256, 256>>>(wq, wk, wv, wo, w1, w2);

    ln_kernel<<<TOK, 256>>>(x, ln1_g, ln1_b, h);

    // fused QKV: 24 x 32 CTAs
    qkv_gemm<<<dim3(24, TOK / 128), 256, GSMEM>>>(h, bq, bk, bv, q, k, v);

    attn_tc<<<dim3(SEQ / 64, 2 * NHEAD), 128, ATTN_SMEM>>>(q, k, v, at);

    dim3 gE(EMB / 128, TOK / 128);       // (8, 32)
    tf32_gemm<0, 0><<<gE, 256, GSMEM>>>(at, dwo, bo, x, x1, TOK, EMB, EMB);

    ln_kernel<<<TOK, 256>>>(x1, ln2_g, ln2_b, h2);

    dim3 gF1(FFD / 128, TOK / 128);      // (32, 32)
    tf32_gemm<1, 1><<<gF1, 256, GSMEM>>>(h2, dw1, b1, nullptr, ff, TOK, FFD, EMB);
    tf32_gemm<0, 0><<<gE, 256, GSMEM>>>(ff, dw2, b2, x1, out, TOK, EMB, FFD);
}

// round 6
// speedup vs baseline: 1.1225x; 1.1225x over previous
#include <cuda_runtime.h>
#include <math.h>
#include <cstdint>

#define TOK   4096          // B*S
#define SEQ   2048
#define EMB   1024
#define NHEAD 16
#define HDIM  64
#define FFD   4096

// -------- scratch ----
__device__ float g_h  [TOK * EMB];
__device__ float g_q  [TOK * EMB];
__device__ float g_k  [TOK * EMB];
__device__ float g_v  [TOK * EMB];
__device__ float g_at [TOK * EMB];
__device__ float g_x1 [TOK * EMB];
__device__ float g_h2 [TOK * EMB];
__device__ float g_ff [TOK * FFD];
// tf32-rounded weights
__device__ float g_wq [EMB * EMB];
__device__ float g_wk [EMB * EMB];
__device__ float g_wv [EMB * EMB];
__device__ float g_wo [EMB * EMB];
__device__ float g_w1 [EMB * FFD];
__device__ float g_w2 [FFD * EMB];

// --------------------------- helpers ------------------------------------------
__device__ __forceinline__ float to_tf32(float x) {
    float r;
    asm("cvt.rna.tf32.f32 %0, %1;" : "=f"(r) : "f"(x));
    return r;
}
__device__ __forceinline__ float4 cvt4(float4 v) {
    return make_float4(to_tf32(v.x), to_tf32(v.y), to_tf32(v.z), to_tf32(v.w));
}
__device__ __forceinline__ uint32_t smem_u32(const void* p) {
    uint32_t a;
    asm("{ .reg .u64 t; cvta.to.shared.u64 t, %1; cvt.u32.u64 %0, t; }" : "=r"(a) : "l"(p));
    return a;
}
__device__ __forceinline__ void cp_async16(uint32_t dst, const void* src) {
    asm volatile("cp.async.cg.shared.global [%0], [%1], 16;" :: "r"(dst), "l"(src));
}
__device__ __forceinline__ void cp_commit() {
    asm volatile("cp.async.commit_group;" ::: "memory");
}
__device__ __forceinline__ void cp_wait2() {
    asm volatile("cp.async.wait_group 2;" ::: "memory");
}
__device__ __forceinline__ void mma_tf32(float* d, const float* a, const float* b) {
    asm volatile(
        "mma.sync.aligned.m16n8k8.row.col.f32.tf32.tf32.f32 "
        "{%0,%1,%2,%3},{%4,%5,%6,%7},{%8,%9},{%0,%1,%2,%3};"
        : "+f"(d[0]), "+f"(d[1]), "+f"(d[2]), "+f"(d[3])
        : "r"(__float_as_uint(a[0])), "r"(__float_as_uint(a[1])),
          "r"(__float_as_uint(a[2])), "r"(__float_as_uint(a[3])),
          "r"(__float_as_uint(b[0])), "r"(__float_as_uint(b[1])));
}

// ------------------------- weight tf32 conversion -----------------------------
__global__ void cvt_weights(const float* __restrict__ wq, const float* __restrict__ wk,
                            const float* __restrict__ wv, const float* __restrict__ wo,
                            const float* __restrict__ w1, const float* __restrict__ w2) {
    const int Q1 = EMB * EMB / 4;
    int i = blockIdx.x * blockDim.x + threadIdx.x;
    const float4* src;
    float4* dst;
    int off;
    if (i < Q1)            { src = (const float4*)wq; dst = (float4*)g_wq; off = i; }
    else if (i < 2 * Q1)   { src = (const float4*)wk; dst = (float4*)g_wk; off = i - Q1; }
    else if (i < 3 * Q1)   { src = (const float4*)wv; dst = (float4*)g_wv; off = i - 2 * Q1; }
    else if (i < 4 * Q1)   { src = (const float4*)wo; dst = (float4*)g_wo; off = i - 3 * Q1; }
    else if (i < 8 * Q1)   { src = (const float4*)w1; dst = (float4*)g_w1; off = i - 4 * Q1; }
    else                   { src = (const float4*)w2; dst = (float4*)g_w2; off = i - 8 * Q1; }
    dst[off] = cvt4(src[off]);
}

// ------------------------------- LayerNorm (tf32-rounded out) -----------------
__global__ void ln_kernel(const float* __restrict__ x, const float* __restrict__ g,
                          const float* __restrict__ b, float* __restrict__ out) {
    int t = blockIdx.x;
    int tid = threadIdx.x;
    const float* row = x + (size_t)t * EMB;
    float vals[4];
    float sum = 0.f, sq = 0.f;
#pragma unroll
    for (int it = 0; it < 4; it++) {
        float v = row[tid + it * 256];
        vals[it] = v; sum += v; sq += v * v;
    }
    __shared__ float s1[256], s2[256];
    s1[tid] = sum; s2[tid] = sq;
    __syncthreads();
    for (int st = 128; st > 0; st >>= 1) {
        if (tid < st) { s1[tid] += s1[tid + st]; s2[tid] += s2[tid + st]; }
        __syncthreads();
    }
    float mu   = s1[0] * (1.f / EMB);
    float var  = s2[0] * (1.f / EMB) - mu * mu;
    float rstd = rsqrtf(var + 1e-5f);
#pragma unroll
    for (int it = 0; it < 4; it++) {
        int i = tid + it * 256;
        out[(size_t)t * EMB + i] = to_tf32((vals[it] - mu) * rstd * g[i] + b[i]);
    }
}

// --------------- tf32 mma GEMM, cp.async 4-stage, BK=16, 2 CTA/SM -------------
// A, W pre-rounded tf32. 128x128 tile, 256 threads (8 warps, 2x4), warp 64x32.
#define AST   20                       // A row stride (floats), 80B
#define BST   136                      // B row stride (floats), 544B
#define ABYTES (128 * AST * 4)         // 10240
#define BBYTES (16 * BST * 4)          // 8704
#define NSTG   4
#define GSMEM  (NSTG * (ABYTES + BBYTES))   // 75776

template <int ACT, int ROUND>
__device__ __forceinline__
void gemm_core(const float* __restrict__ A, const float* __restrict__ W,
               const float* __restrict__ bias, const float* __restrict__ res,
               float* __restrict__ C, int M, int N, int K, int m0, int n0,
               char* smem) {
    uint32_t sbase = smem_u32(smem);
    int tid  = threadIdx.x;
    int lane = tid & 31, warp = tid >> 5;
    int g = lane >> 2, t = lane & 3;
    int wm = (warp >> 2) * 64;
    int wn = (warp & 3) * 32;

    // cp.async mappings: A 128x16 (2 thr/row, 8 floats each = 2x16B)
    int a_row = tid >> 1;
    int a_cb  = (tid & 1) * 8;
    // B 16x128 (16 thr/row, 8 floats each)
    int b_row = tid >> 4;
    int b_cb  = (tid & 15) * 8;

    const float* Ap = A + (size_t)(m0 + a_row) * K + a_cb;
    const float* Wp = W + (size_t)b_row * N + n0 + b_cb;
    uint32_t a_dst0 = sbase + a_row * (AST * 4) + a_cb * 4;
    uint32_t b_dst0 = sbase + NSTG * ABYTES + b_row * (BST * 4) + b_cb * 4;

    int nkb = K >> 4;

#define ISSUE(kb, s)                                                           \
    do {                                                                       \
        const float* asrc = Ap + (kb) * 16;                                    \
        const float* bsrc = Wp + (size_t)(kb) * 16 * N;                        \
        uint32_t ad = a_dst0 + (s) * ABYTES;                                   \
        uint32_t bd = b_dst0 + (s) * BBYTES;                                   \
        cp_async16(ad,      asrc);      cp_async16(ad + 16, asrc + 4);         \
        cp_async16(bd,      bsrc);      cp_async16(bd + 16, bsrc + 4);         \
    } while (0)

#pragma unroll
    for (int s = 0; s < NSTG - 1; s++) {
        if (s < nkb) ISSUE(s, s);
        cp_commit();
    }

    float acc[4][4][4] = {};

    for (int kb = 0; kb < nkb; kb++) {
        cp_wait2();
        __syncthreads();

        // issue next stage first (target (kb+3)%4 was drained last iteration)
        if (kb + NSTG - 1 < nkb) ISSUE(kb + NSTG - 1, (kb + NSTG - 1) & (NSTG - 1));
        cp_commit();

        int buf = kb & (NSTG - 1);
        const float* As = (const float*)(smem + buf * ABYTES);
        const float* Bs = (const float*)(smem + NSTG * ABYTES + buf * BBYTES);

#pragma unroll
        for (int kk = 0; kk < 2; kk++) {
            float a[4][4], b[4][2];
#pragma unroll
            for (int mf = 0; mf < 4; mf++) {
                int r = wm + mf * 16;
                a[mf][0] = As[(r + g)     * AST + kk * 8 + t];
                a[mf][1] = As[(r + g + 8) * AST + kk * 8 + t];
                a[mf][2] = As[(r + g)     * AST + kk * 8 + t + 4];
                a[mf][3] = As[(r + g + 8) * AST + kk * 8 + t + 4];
            }
#pragma unroll
            for (int nf = 0; nf < 4; nf++) {
                int c = wn + nf * 8 + g;
                b[nf][0] = Bs[(kk * 8 + t)     * BST + c];
                b[nf][1] = Bs[(kk * 8 + t + 4) * BST + c];
            }
#pragma unroll
            for (int mf = 0; mf < 4; mf++)
#pragma unroll
                for (int nf = 0; nf < 4; nf++)
                    mma_tf32(acc[mf][nf], a[mf], b[nf]);
        }
    }
#undef ISSUE

    // epilogue
#pragma unroll
    for (int mf = 0; mf < 4; mf++) {
#pragma unroll
        for (int nf = 0; nf < 4; nf++) {
            int mA = m0 + wm + mf * 16 + g;
            int mB = mA + 8;
            int n_ = n0 + wn + nf * 8 + 2 * t;
            float bn0 = bias[n_], bn1 = bias[n_ + 1];

            float v00 = acc[mf][nf][0] + bn0;
            float v01 = acc[mf][nf][1] + bn1;
            float v10 = acc[mf][nf][2] + bn0;
            float v11 = acc[mf][nf][3] + bn1;
            if (res) {
                const float2 r0 = *(const float2*)(res + (size_t)mA * N + n_);
                const float2 r1 = *(const float2*)(res + (size_t)mB * N + n_);
                v00 += r0.x; v01 += r0.y; v10 += r1.x; v11 += r1.y;
            }
            if (ACT == 1) {
                v00 = 0.5f * v00 * (1.f + erff(v00 * 0.70710678118654752f));
                v01 = 0.5f * v01 * (1.f + erff(v01 * 0.70710678118654752f));
                v10 = 0.5f * v10 * (1.f + erff(v10 * 0.70710678118654752f));
                v11 = 0.5f * v11 * (1.f + erff(v11 * 0.70710678118654752f));
            }
            if (ROUND == 1) {
                v00 = to_tf32(v00); v01 = to_tf32(v01);
                v10 = to_tf32(v10); v11 = to_tf32(v11);
            }
            *(float2*)(C + (size_t)mA * N + n_) = make_float2(v00, v01);
            *(float2*)(C + (size_t)mB * N + n_) = make_float2(v10, v11);
        }
    }
}

template <int ACT, int ROUND>
__global__ __launch_bounds__(256, 2)
void tf32_gemm(const float* __restrict__ A, const float* __restrict__ W,
               const float* __restrict__ bias, const float* __restrict__ res,
               float* __restrict__ C, int M, int N, int K) {
    extern __shared__ char smem[];
    gemm_core<ACT, ROUND>(A, W, bias, res, C, M, N, K,
                          blockIdx.y * 128, blockIdx.x * 128, smem);
}

// fused QKV: gridDim.x = 24 (3 weights x 8 n-blocks)
__global__ __launch_bounds__(256, 2)
void qkv_gemm(const float* __restrict__ A,
              const float* __restrict__ bq, const float* __restrict__ bk,
              const float* __restrict__ bv,
              float* __restrict__ Qo, float* __restrict__ Ko, float* __restrict__ Vo) {
    extern __shared__ char smem[];
    int wsel = blockIdx.x >> 3;
    int n0   = (blockIdx.x & 7) * 128;
    const float* W;
    const float* bias;
    float* C;
    if (wsel == 0)      { W = g_wq; bias = bq; C = Qo; }
    else if (wsel == 1) { W = g_wk; bias = bk; C = Ko; }
    else                { W = g_wv; bias = bv; C = Vo; }
    gemm_core<0, 0>(A, W, bias, nullptr, C, TOK, EMB, EMB,
                    blockIdx.y * 128, n0, smem);
}

// -------------------- Tensor-core flash attention (tf32) ----------------------
#define KST 68
#define VST 72
#define SST 68

__global__ __launch_bounds__(128)
void attn_tc(const float* __restrict__ Q, const float* __restrict__ K,
             const float* __restrict__ V, float* __restrict__ O) {
    extern __shared__ float sm[];
    float* Ks = sm;
    float* Vs = Ks + 64 * KST;
    float* Ss = Vs + 64 * VST;

    int qt = (int)gridDim.x - 1 - (int)blockIdx.x;
    int bh = blockIdx.y;
    int bb = bh >> 4, hh = bh & 15;
    int tid  = threadIdx.x;
    int warp = tid >> 5, lane = tid & 31;
    int g = lane >> 2, t = lane & 3;
    int r0 = warp * 16;

    size_t base = (size_t)bb * SEQ * EMB + (size_t)hh * HDIM;

#pragma unroll
    for (int it = 0; it < 8; it++) {
        int r = (tid >> 4) + it * 8;
        int c = (tid & 15) * 4;
        float4 v = *(const float4*)(Q + base + (size_t)(qt * 64 + r) * EMB + c);
        float4 w = make_float4(to_tf32(v.x * 0.125f), to_tf32(v.y * 0.125f),
                               to_tf32(v.z * 0.125f), to_tf32(v.w * 0.125f));
        *(float4*)&Ss[r * SST + c] = w;
    }
    __syncthreads();

    float qf[8][4];
#pragma unroll
    for (int kc = 0; kc < 8; kc++) {
        qf[kc][0] = Ss[(r0 + g)     * SST + kc * 8 + t];
        qf[kc][1] = Ss[(r0 + g + 8) * SST + kc * 8 + t];
        qf[kc][2] = Ss[(r0 + g)     * SST + kc * 8 + t + 4];
        qf[kc][3] = Ss[(r0 + g + 8) * SST + kc * 8 + t + 4];
    }

    float o[8][4] = {};
    float m0 = -1e30f, m1 = -1e30f, l0 = 0.f, l1 = 0.f;

    for (int kt = 0; kt <= qt; kt++) {
#pragma unroll
        for (int it = 0; it < 8; it++) {
            int r = (tid >> 4) + it * 8;
            int c = (tid & 15) * 4;
            size_t go = base + (size_t)(kt * 64 + r) * EMB + c;
            float4 kv = *(const float4*)(K + go);
            float4 vv = *(const float4*)(V + go);
            *(float4*)&Ks[r * KST + c] = cvt4(kv);
            *(float4*)&Vs[r * VST + c] = cvt4(vv);
        }
        __syncthreads();

        float s[8][4];
#pragma unroll
        for (int nf = 0; nf < 8; nf++) {
            s[nf][0] = s[nf][1] = s[nf][2] = s[nf][3] = 0.f;
            const float* kr = &Ks[(nf * 8 + g) * KST];
#pragma unroll
            for (int kc = 0; kc < 8; kc++) {
                float b[2] = { kr[kc * 8 + t], kr[kc * 8 + t + 4] };
                mma_tf32(s[nf], qf[kc], b);
            }
        }

        if (kt == qt) {
            int rowA = r0 + g, rowB = r0 + g + 8;
#pragma unroll
            for (int nf = 0; nf < 8; nf++) {
                int c0 = nf * 8 + 2 * t, c1 = c0 + 1;
                if (c0 > rowA) s[nf][0] = -1e30f;
                if (c1 > rowA) s[nf][1] = -1e30f;
                if (c0 > rowB) s[nf][2] = -1e30f;
                if (c1 > rowB) s[nf][3] = -1e30f;
            }
        }

        float mx0 = -1e30f, mx1 = -1e30f;
#pragma unroll
        for (int nf = 0; nf < 8; nf++) {
            mx0 = fmaxf(mx0, fmaxf(s[nf][0], s[nf][1]));
            mx1 = fmaxf(mx1, fmaxf(s[nf][2], s[nf][3]));
        }
        mx0 = fmaxf(mx0, __shfl_xor_sync(0xffffffffu, mx0, 1));
        mx0 = fmaxf(mx0, __shfl_xor_sync(0xffffffffu, mx0, 2));
        mx1 = fmaxf(mx1, __shfl_xor_sync(0xffffffffu, mx1, 1));
        mx1 = fmaxf(mx1, __shfl_xor_sync(0xffffffffu, mx1, 2));

        float m0n = fmaxf(m0, mx0), m1n = fmaxf(m1, mx1);
        float rs0 = __expf(m0 - m0n), rs1 = __expf(m1 - m1n);
        m0 = m0n; m1 = m1n;

        float sum0 = 0.f, sum1 = 0.f;
#pragma unroll
        for (int nf = 0; nf < 8; nf++) {
            s[nf][0] = __expf(s[nf][0] - m0);
            s[nf][1] = __expf(s[nf][1] - m0);
            s[nf][2] = __expf(s[nf][2] - m1);
            s[nf][3] = __expf(s[nf][3] - m1);
            sum0 += s[nf][0] + s[nf][1];
            sum1 += s[nf][2] + s[nf][3];
        }
        sum0 += __shfl_xor_sync(0xffffffffu, sum0, 1);
        sum0 += __shfl_xor_sync(0xffffffffu, sum0, 2);
        sum1 += __shfl_xor_sync(0xffffffffu, sum1, 1);
        sum1 += __shfl_xor_sync(0xffffffffu, sum1, 2);
        l0 = l0 * rs0 + sum0;
        l1 = l1 * rs1 + sum1;

        __syncwarp();
#pragma unroll
        for (int nf = 0; nf < 8; nf++) {
            int c = nf * 8 + 2 * t;
            *(float2*)&Ss[(r0 + g)     * SST + c] =
                make_float2(to_tf32(s[nf][0]), to_tf32(s[nf][1]));
            *(float2*)&Ss[(r0 + g + 8) * SST + c] =
                make_float2(to_tf32(s[nf][2]), to_tf32(s[nf][3]));
        }
        __syncwarp();

#pragma unroll
        for (int nf = 0; nf < 8; nf++) {
            o[nf][0] *= rs0; o[nf][1] *= rs0;
            o[nf][2] *= rs1; o[nf][3] *= rs1;
        }
#pragma unroll
        for (int kc = 0; kc < 8; kc++) {
            float pf[4];
            pf[0] = Ss[(r0 + g)     * SST + kc * 8 + t];
            pf[1] = Ss[(r0 + g + 8) * SST + kc * 8 + t];
            pf[2] = Ss[(r0 + g)     * SST + kc * 8 + t + 4];
            pf[3] = Ss[(r0 + g + 8) * SST + kc * 8 + t + 4];
            const float* v0 = &Vs[(kc * 8 + t)     * VST];
            const float* v1 = &Vs[(kc * 8 + t + 4) * VST];
#pragma unroll
            for (int nf = 0; nf < 8; nf++) {
                float b[2] = { v0[nf * 8 + g], v1[nf * 8 + g] };
                mma_tf32(o[nf], pf, b);
            }
        }
        __syncthreads();
    }

    float il0 = 1.f / l0, il1 = 1.f / l1;
    int rowA = qt * 64 + r0 + g;
    int rowB = rowA + 8;
#pragma unroll
    for (int nf = 0; nf < 8; nf++) {
        int c = nf * 8 + 2 * t;
        *(float2*)(O + base + (size_t)rowA * EMB + c) =
            make_float2(to_tf32(o[nf][0] * il0), to_tf32(o[nf][1] * il0));
        *(float2*)(O + base + (size_t)rowB * EMB + c) =
            make_float2(to_tf32(o[nf][2] * il1), to_tf32(o[nf][3] * il1));
    }
}

// ------------------------------- launch --------------------------------------
extern "C" void kernel_launch(void* const* d_in, const int* in_sizes, int n_in,
                              void* d_out, int out_size) {
    const float* x     = (const float*)d_in[0];
    const float* ln1_g = (const float*)d_in[2];
    const float* ln1_b = (const float*)d_in[3];
    const float* wq    = (const float*)d_in[4];
    const float* bq    = (const float*)d_in[5];
    const float* wk    = (const float*)d_in[6];
    const float* bk    = (const float*)d_in[7];
    const float* wv    = (const float*)d_in[8];
    const float* bv    = (const float*)d_in[9];
    const float* wo    = (const float*)d_in[10];
    const float* bo    = (const float*)d_in[11];
    const float* ln2_g = (const float*)d_in[12];
    const float* ln2_b = (const float*)d_in[13];
    const float* w1    = (const float*)d_in[14];
    const float* b1    = (const float*)d_in[15];
    const float* w2    = (const float*)d_in[16];
    const float* b2    = (const float*)d_in[17];
    float* out = (float*)d_out;

    float *h, *q, *k, *v, *at, *x1, *h2, *ff;
    cudaGetSymbolAddress((void**)&h,  g_h);
    cudaGetSymbolAddress((void**)&q,  g_q);
    cudaGetSymbolAddress((void**)&k,  g_k);
    cudaGetSymbolAddress((void**)&v,  g_v);
    cudaGetSymbolAddress((void**)&at, g_at);
    cudaGetSymbolAddress((void**)&x1, g_x1);
    cudaGetSymbolAddress((void**)&h2, g_h2);
    cudaGetSymbolAddress((void**)&ff, g_ff);
    float *dwo, *dw1, *dw2;
    cudaGetSymbolAddress((void**)&dwo, g_wo);
    cudaGetSymbolAddress((void**)&dw1, g_w1);
    cudaGetSymbolAddress((void**)&dw2, g_w2);

    const int ATTN_SMEM = (64 * KST + 64 * VST + 64 * SST) * sizeof(float);
    cudaFuncSetAttribute(attn_tc, cudaFuncAttributeMaxDynamicSharedMemorySize, ATTN_SMEM);
    cudaFuncSetAttribute(tf32_gemm<0, 0>, cudaFuncAttributeMaxDynamicSharedMemorySize, GSMEM);
    cudaFuncSetAttribute(tf32_gemm<1, 1>, cudaFuncAttributeMaxDynamicSharedMemorySize, GSMEM);
    cudaFuncSetAttribute(qkv_gemm, cudaFuncAttributeMaxDynamicSharedMemorySize, GSMEM);

    cvt_weights<<<(3 * EMB * EMB) / 256, 256>>>(wq, wk, wv, wo, w1, w2);

    ln_kernel<<<TOK, 256>>>(x, ln1_g, ln1_b, h);

    qkv_gemm<<<dim3(24, TOK / 128), 256, GSMEM>>>(h, bq, bk, bv, q, k, v);

    attn_tc<<<dim3(SEQ / 64, 2 * NHEAD), 128, ATTN_SMEM>>>(q, k, v, at);

    dim3 gE(EMB / 128, TOK / 128);
    tf32_gemm<0, 0><<<gE, 256, GSMEM>>>(at, dwo, bo, x, x1, TOK, EMB, EMB);

    ln_kernel<<<TOK, 256>>>(x1, ln2_g, ln2_b, h2);

    dim3 gF1(FFD / 128, TOK / 128);
    tf32_gemm<1, 1><<<gF1, 256, GSMEM>>>(h2, dw1, b1, nullptr, ff, TOK, FFD, EMB);
    tf32_gemm<0, 0><<<gE, 256, GSMEM>>>(ff, dw2, b2, x1, out, TOK, EMB, FFD);
}

// round 7
// speedup vs baseline: 1.6915x; 1.5069x over previous
#include <cuda_runtime.h>
#include <cuda_fp16.h>
#include <math.h>
#include <cstdint>

#define TOK   4096          // B*S
#define SEQ   2048
#define EMB   1024
#define NHEAD 16
#define HDIM  64
#define FFD   4096

// -------- scratch ----
__device__ __half g_h  [TOK * EMB];
__device__ __half g_q  [TOK * EMB];
__device__ __half g_k  [TOK * EMB];
__device__ __half g_v  [TOK * EMB];
__device__ __half g_at [TOK * EMB];
__device__ float  g_x1 [TOK * EMB];
__device__ __half g_h2 [TOK * EMB];
__device__ __half g_ff [TOK * FFD];
// fp16 weights, TRANSPOSED to [N][K]
__device__ __half g_wqT[EMB * EMB];
__device__ __half g_wkT[EMB * EMB];
__device__ __half g_wvT[EMB * EMB];
__device__ __half g_woT[EMB * EMB];
__device__ __half g_w1T[FFD * EMB];   // [N=FFD][K=EMB]
__device__ __half g_w2T[EMB * FFD];   // [N=EMB][K=FFD]

// --------------------------- helpers ------------------------------------------
__device__ __forceinline__ float to_tf32(float x) {
    float r;
    asm("cvt.rna.tf32.f32 %0, %1;" : "=f"(r) : "f"(x));
    return r;
}
__device__ __forceinline__ uint32_t smem_u32(const void* p) {
    uint32_t a;
    asm("{ .reg .u64 t; cvta.to.shared.u64 t, %1; cvt.u32.u64 %0, t; }" : "=r"(a) : "l"(p));
    return a;
}
__device__ __forceinline__ void cp_async16(uint32_t dst, const void* src) {
    asm volatile("cp.async.cg.shared.global [%0], [%1], 16;" :: "r"(dst), "l"(src));
}
__device__ __forceinline__ void cp_commit() {
    asm volatile("cp.async.commit_group;" ::: "memory");
}
__device__ __forceinline__ void cp_wait2() {
    asm volatile("cp.async.wait_group 2;" ::: "memory");
}
__device__ __forceinline__ void mma_f16(float* d, const uint32_t* a, const uint32_t* b) {
    asm volatile(
        "mma.sync.aligned.m16n8k16.row.col.f32.f16.f16.f32 "
        "{%0,%1,%2,%3},{%4,%5,%6,%7},{%8,%9},{%0,%1,%2,%3};"
        : "+f"(d[0]), "+f"(d[1]), "+f"(d[2]), "+f"(d[3])
        : "r"(a[0]), "r"(a[1]), "r"(a[2]), "r"(a[3]), "r"(b[0]), "r"(b[1]));
}
__device__ __forceinline__ void mma_tf32(float* d, const float* a, const float* b) {
    asm volatile(
        "mma.sync.aligned.m16n8k8.row.col.f32.tf32.tf32.f32 "
        "{%0,%1,%2,%3},{%4,%5,%6,%7},{%8,%9},{%0,%1,%2,%3};"
        : "+f"(d[0]), "+f"(d[1]), "+f"(d[2]), "+f"(d[3])
        : "r"(__float_as_uint(a[0])), "r"(__float_as_uint(a[1])),
          "r"(__float_as_uint(a[2])), "r"(__float_as_uint(a[3])),
          "r"(__float_as_uint(b[0])), "r"(__float_as_uint(b[1])));
}

// -------------------- weight convert + transpose (fp32[K][N] -> fp16[N][K]) ---
__global__ void cvt_w(const float* __restrict__ W, __half* __restrict__ WT,
                      int K, int N) {
    __shared__ float tile[32][33];
    int tx = threadIdx.x, ty = threadIdx.y;     // 32 x 8
    int n0 = blockIdx.x * 32, k0 = blockIdx.y * 32;
#pragma unroll
    for (int j = 0; j < 4; j++)
        tile[ty + j * 8][tx] = W[(size_t)(k0 + ty + j * 8) * N + n0 + tx];
    __syncthreads();
#pragma unroll
    for (int j = 0; j < 4; j++)
        WT[(size_t)(n0 + ty + j * 8) * K + k0 + tx] = __float2half(tile[tx][ty + j * 8]);
}

// ------------------------------- LayerNorm (fp16 out) -------------------------
__global__ void ln_kernel(const float* __restrict__ x, const float* __restrict__ g,
                          const float* __restrict__ b, __half* __restrict__ out) {
    int t = blockIdx.x;
    int tid = threadIdx.x;
    const float* row = x + (size_t)t * EMB;
    float vals[4];
    float sum = 0.f, sq = 0.f;
#pragma unroll
    for (int it = 0; it < 4; it++) {
        float v = row[tid + it * 256];
        vals[it] = v; sum += v; sq += v * v;
    }
    __shared__ float s1[256], s2[256];
    s1[tid] = sum; s2[tid] = sq;
    __syncthreads();
    for (int st = 128; st > 0; st >>= 1) {
        if (tid < st) { s1[tid] += s1[tid + st]; s2[tid] += s2[tid + st]; }
        __syncthreads();
    }
    float mu   = s1[0] * (1.f / EMB);
    float var  = s2[0] * (1.f / EMB) - mu * mu;
    float rstd = rsqrtf(var + 1e-5f);
#pragma unroll
    for (int it = 0; it < 4; it++) {
        int i = tid + it * 256;
        out[(size_t)t * EMB + i] = __float2half((vals[it] - mu) * rstd * g[i] + b[i]);
    }
}

// ----------------- fp16 mma GEMM, cp.async 4-stage, BK=32 ---------------------
// A [M][K] fp16, WT [N][K] fp16. 128x128 tile, 256 thr (8 warps 2x4), warp 64x32.
// Row stride 40 halves (80B = 20 words); frag banks 20g+t verified conflict-free.
#define HROW  40
#define ABY   (128 * 80)     // 10240 bytes/stage
#define BBY   (128 * 80)
#define NSTG  4
#define GSM   (NSTG * (ABY + BBY))   // 81920

template <int ACT, int OH>
__device__ __forceinline__
void hgemm_core(const __half* __restrict__ A, const __half* __restrict__ WT,
                const float* __restrict__ bias, const float* __restrict__ res,
                void* __restrict__ Cv, int M, int N, int K, int m0, int n0,
                char* smem) {
    uint32_t sbase = smem_u32(smem);
    int tid  = threadIdx.x;
    int lane = tid & 31, warp = tid >> 5;
    int g = lane >> 2, t = lane & 3;
    int wm = (warp >> 2) * 64;
    int wn = (warp & 3) * 32;

    // cp.async mapping: 128 rows x 64B data; 2 threads/row, 32B each
    int rrow = tid >> 1;
    int rc   = (tid & 1) * 16;      // half offset within k-slice

    const __half* Ap = A  + (size_t)(m0 + rrow) * K + rc;
    const __half* Bp = WT + (size_t)(n0 + rrow) * K + rc;
    uint32_t a_dst0 = sbase + rrow * 80 + rc * 2;
    uint32_t b_dst0 = sbase + NSTG * ABY + rrow * 80 + rc * 2;

    int nkb = K >> 5;

#define ISSUEH(kb, s)                                                          \
    do {                                                                       \
        const __half* asrc = Ap + (size_t)(kb) * 32;                           \
        const __half* bsrc = Bp + (size_t)(kb) * 32;                           \
        uint32_t ad = a_dst0 + (s) * ABY;                                      \
        uint32_t bd = b_dst0 + (s) * BBY;                                      \
        cp_async16(ad,      asrc);      cp_async16(ad + 16, asrc + 8);         \
        cp_async16(bd,      bsrc);      cp_async16(bd + 16, bsrc + 8);         \
    } while (0)

#pragma unroll
    for (int s = 0; s < NSTG - 1; s++) {
        if (s < nkb) ISSUEH(s, s);
        cp_commit();
    }

    float acc[4][4][4] = {};

    for (int kb = 0; kb < nkb; kb++) {
        cp_wait2();
        __syncthreads();

        if (kb + NSTG - 1 < nkb) ISSUEH(kb + NSTG - 1, (kb + NSTG - 1) & (NSTG - 1));
        cp_commit();

        int buf = kb & (NSTG - 1);
        const uint32_t* AsW = (const uint32_t*)(smem + buf * ABY);
        const uint32_t* BsW = (const uint32_t*)(smem + NSTG * ABY + buf * BBY);

#pragma unroll
        for (int ks = 0; ks < 2; ks++) {
            uint32_t a[4][4], b[4][2];
#pragma unroll
            for (int mf = 0; mf < 4; mf++) {
                int r = wm + mf * 16;
                a[mf][0] = AsW[(r + g)     * 20 + ks * 8 + t];
                a[mf][1] = AsW[(r + g + 8) * 20 + ks * 8 + t];
                a[mf][2] = AsW[(r + g)     * 20 + ks * 8 + t + 4];
                a[mf][3] = AsW[(r + g + 8) * 20 + ks * 8 + t + 4];
            }
#pragma unroll
            for (int nf = 0; nf < 4; nf++) {
                int c = wn + nf * 8 + g;
                b[nf][0] = BsW[c * 20 + ks * 8 + t];
                b[nf][1] = BsW[c * 20 + ks * 8 + t + 4];
            }
#pragma unroll
            for (int mf = 0; mf < 4; mf++)
#pragma unroll
                for (int nf = 0; nf < 4; nf++)
                    mma_f16(acc[mf][nf], a[mf], b[nf]);
        }
    }
#undef ISSUEH

    // epilogue
#pragma unroll
    for (int mf = 0; mf < 4; mf++) {
#pragma unroll
        for (int nf = 0; nf < 4; nf++) {
            int mA = m0 + wm + mf * 16 + g;
            int mB = mA + 8;
            int n_ = n0 + wn + nf * 8 + 2 * t;
            float bn0 = bias[n_], bn1 = bias[n_ + 1];

            float v00 = acc[mf][nf][0] + bn0;
            float v01 = acc[mf][nf][1] + bn1;
            float v10 = acc[mf][nf][2] + bn0;
            float v11 = acc[mf][nf][3] + bn1;
            if (res) {
                const float2 r0 = *(const float2*)(res + (size_t)mA * N + n_);
                const float2 r1 = *(const float2*)(res + (size_t)mB * N + n_);
                v00 += r0.x; v01 += r0.y; v10 += r1.x; v11 += r1.y;
            }
            if (ACT == 1) {
                v00 = 0.5f * v00 * (1.f + erff(v00 * 0.70710678118654752f));
                v01 = 0.5f * v01 * (1.f + erff(v01 * 0.70710678118654752f));
                v10 = 0.5f * v10 * (1.f + erff(v10 * 0.70710678118654752f));
                v11 = 0.5f * v11 * (1.f + erff(v11 * 0.70710678118654752f));
            }
            if (OH == 1) {
                __half* Ch = (__half*)Cv;
                *(__half2*)(Ch + (size_t)mA * N + n_) = __floats2half2_rn(v00, v01);
                *(__half2*)(Ch + (size_t)mB * N + n_) = __floats2half2_rn(v10, v11);
            } else {
                float* Cf = (float*)Cv;
                *(float2*)(Cf + (size_t)mA * N + n_) = make_float2(v00, v01);
                *(float2*)(Cf + (size_t)mB * N + n_) = make_float2(v10, v11);
            }
        }
    }
}

template <int ACT, int OH>
__global__ __launch_bounds__(256, 2)
void h_gemm(const __half* __restrict__ A, const __half* __restrict__ WT,
            const float* __restrict__ bias, const float* __restrict__ res,
            void* __restrict__ C, int M, int N, int K) {
    extern __shared__ char smem[];
    hgemm_core<ACT, OH>(A, WT, bias, res, C, M, N, K,
                        blockIdx.y * 128, blockIdx.x * 128, smem);
}

// fused QKV: gridDim.x = 24 (3 weights x 8 n-blocks)
__global__ __launch_bounds__(256, 2)
void qkv_gemm(const __half* __restrict__ A,
              const float* __restrict__ bq, const float* __restrict__ bk,
              const float* __restrict__ bv,
              __half* __restrict__ Qo, __half* __restrict__ Ko,
              __half* __restrict__ Vo) {
    extern __shared__ char smem[];
    int wsel = blockIdx.x >> 3;
    int n0   = (blockIdx.x & 7) * 128;
    const __half* W;
    const float* bias;
    __half* C;
    if (wsel == 0)      { W = g_wqT; bias = bq; C = Qo; }
    else if (wsel == 1) { W = g_wkT; bias = bk; C = Ko; }
    else                { W = g_wvT; bias = bv; C = Vo; }
    hgemm_core<0, 1>(A, W, bias, nullptr, C, TOK, EMB, EMB,
                     blockIdx.y * 128, n0, smem);
}

// -------------------- flash attention (tf32 mma, fp16 I/O) --------------------
#define KST 68
#define VST 72
#define SST 68

__global__ __launch_bounds__(128)
void attn_tc(const __half* __restrict__ Q, const __half* __restrict__ K,
             const __half* __restrict__ V, __half* __restrict__ O) {
    extern __shared__ float sm[];
    float* Ks = sm;
    float* Vs = Ks + 64 * KST;
    float* Ss = Vs + 64 * VST;

    int qt = (int)gridDim.x - 1 - (int)blockIdx.x;
    int bh = blockIdx.y;
    int bb = bh >> 4, hh = bh & 15;
    int tid  = threadIdx.x;
    int warp = tid >> 5, lane = tid & 31;
    int g = lane >> 2, t = lane & 3;
    int r0 = warp * 16;

    size_t base = (size_t)bb * SEQ * EMB + (size_t)hh * HDIM;

#pragma unroll
    for (int it = 0; it < 8; it++) {
        int r = (tid >> 4) + it * 8;
        int c = (tid & 15) * 4;
        const __half2* qp = (const __half2*)(Q + base + (size_t)(qt * 64 + r) * EMB + c);
        float2 f0 = __half22float2(qp[0]);
        float2 f1 = __half22float2(qp[1]);
        *(float4*)&Ss[r * SST + c] =
            make_float4(f0.x * 0.125f, f0.y * 0.125f, f1.x * 0.125f, f1.y * 0.125f);
    }
    __syncthreads();

    float qf[8][4];
#pragma unroll
    for (int kc = 0; kc < 8; kc++) {
        qf[kc][0] = Ss[(r0 + g)     * SST + kc * 8 + t];
        qf[kc][1] = Ss[(r0 + g + 8) * SST + kc * 8 + t];
        qf[kc][2] = Ss[(r0 + g)     * SST + kc * 8 + t + 4];
        qf[kc][3] = Ss[(r0 + g + 8) * SST + kc * 8 + t + 4];
    }

    float o[8][4] = {};
    float m0 = -1e30f, m1 = -1e30f, l0 = 0.f, l1 = 0.f;

    for (int kt = 0; kt <= qt; kt++) {
#pragma unroll
        for (int it = 0; it < 8; it++) {
            int r = (tid >> 4) + it * 8;
            int c = (tid & 15) * 4;
            size_t go = base + (size_t)(kt * 64 + r) * EMB + c;
            const __half2* kp = (const __half2*)(K + go);
            const __half2* vp = (const __half2*)(V + go);
            float2 k0 = __half22float2(kp[0]), k1 = __half22float2(kp[1]);
            float2 v0 = __half22float2(vp[0]), v1 = __half22float2(vp[1]);
            *(float4*)&Ks[r * KST + c] = make_float4(k0.x, k0.y, k1.x, k1.y);
            *(float4*)&Vs[r * VST + c] = make_float4(v0.x, v0.y, v1.x, v1.y);
        }
        __syncthreads();

        float s[8][4];
#pragma unroll
        for (int nf = 0; nf < 8; nf++) {
            s[nf][0] = s[nf][1] = s[nf][2] = s[nf][3] = 0.f;
            const float* kr = &Ks[(nf * 8 + g) * KST];
#pragma unroll
            for (int kc = 0; kc < 8; kc++) {
                float b[2] = { kr[kc * 8 + t], kr[kc * 8 + t + 4] };
                mma_tf32(s[nf], qf[kc], b);
            }
        }

        if (kt == qt) {
            int rowA = r0 + g, rowB = r0 + g + 8;
#pragma unroll
            for (int nf = 0; nf < 8; nf++) {
                int c0 = nf * 8 + 2 * t, c1 = c0 + 1;
                if (c0 > rowA) s[nf][0] = -1e30f;
                if (c1 > rowA) s[nf][1] = -1e30f;
                if (c0 > rowB) s[nf][2] = -1e30f;
                if (c1 > rowB) s[nf][3] = -1e30f;
            }
        }

        float mx0 = -1e30f, mx1 = -1e30f;
#pragma unroll
        for (int nf = 0; nf < 8; nf++) {
            mx0 = fmaxf(mx0, fmaxf(s[nf][0], s[nf][1]));
            mx1 = fmaxf(mx1, fmaxf(s[nf][2], s[nf][3]));
        }
        mx0 = fmaxf(mx0, __shfl_xor_sync(0xffffffffu, mx0, 1));
        mx0 = fmaxf(mx0, __shfl_xor_sync(0xffffffffu, mx0, 2));
        mx1 = fmaxf(mx1, __shfl_xor_sync(0xffffffffu, mx1, 1));
        mx1 = fmaxf(mx1, __shfl_xor_sync(0xffffffffu, mx1, 2));

        float m0n = fmaxf(m0, mx0), m1n = fmaxf(m1, mx1);
        float rs0 = __expf(m0 - m0n), rs1 = __expf(m1 - m1n);
        m0 = m0n; m1 = m1n;

        float sum0 = 0.f, sum1 = 0.f;
#pragma unroll
        for (int nf = 0; nf < 8; nf++) {
            s[nf][0] = __expf(s[nf][0] - m0);
            s[nf][1] = __expf(s[nf][1] - m0);
            s[nf][2] = __expf(s[nf][2] - m1);
            s[nf][3] = __expf(s[nf][3] - m1);
            sum0 += s[nf][0] + s[nf][1];
            sum1 += s[nf][2] + s[nf][3];
        }
        sum0 += __shfl_xor_sync(0xffffffffu, sum0, 1);
        sum0 += __shfl_xor_sync(0xffffffffu, sum0, 2);
        sum1 += __shfl_xor_sync(0xffffffffu, sum1, 1);
        sum1 += __shfl_xor_sync(0xffffffffu, sum1, 2);
        l0 = l0 * rs0 + sum0;
        l1 = l1 * rs1 + sum1;

        __syncwarp();
#pragma unroll
        for (int nf = 0; nf < 8; nf++) {
            int c = nf * 8 + 2 * t;
            *(float2*)&Ss[(r0 + g)     * SST + c] =
                make_float2(to_tf32(s[nf][0]), to_tf32(s[nf][1]));
            *(float2*)&Ss[(r0 + g + 8) * SST + c] =
                make_float2(to_tf32(s[nf][2]), to_tf32(s[nf][3]));
        }
        __syncwarp();

#pragma unroll
        for (int nf = 0; nf < 8; nf++) {
            o[nf][0] *= rs0; o[nf][1] *= rs0;
            o[nf][2] *= rs1; o[nf][3] *= rs1;
        }
#pragma unroll
        for (int kc = 0; kc < 8; kc++) {
            float pf[4];
            pf[0] = Ss[(r0 + g)     * SST + kc * 8 + t];
            pf[1] = Ss[(r0 + g + 8) * SST + kc * 8 + t];
            pf[2] = Ss[(r0 + g)     * SST + kc * 8 + t + 4];
            pf[3] = Ss[(r0 + g + 8) * SST + kc * 8 + t + 4];
            const float* v0 = &Vs[(kc * 8 + t)     * VST];
            const float* v1 = &Vs[(kc * 8 + t + 4) * VST];
#pragma unroll
            for (int nf = 0; nf < 8; nf++) {
                float b[2] = { v0[nf * 8 + g], v1[nf * 8 + g] };
                mma_tf32(o[nf], pf, b);
            }
        }
        __syncthreads();
    }

    float il0 = 1.f / l0, il1 = 1.f / l1;
    int rowA = qt * 64 + r0 + g;
    int rowB = rowA + 8;
#pragma unroll
    for (int nf = 0; nf < 8; nf++) {
        int c = nf * 8 + 2 * t;
        *(__half2*)(O + base + (size_t)rowA * EMB + c) =
            __floats2half2_rn(o[nf][0] * il0, o[nf][1] * il0);
        *(__half2*)(O + base + (size_t)rowB * EMB + c) =
            __floats2half2_rn(o[nf][2] * il1, o[nf][3] * il1);
    }
}

// ------------------------------- launch --------------------------------------
extern "C" void kernel_launch(void* const* d_in, const int* in_sizes, int n_in,
                              void* d_out, int out_size) {
    const float* x     = (const float*)d_in[0];
    const float* ln1_g = (const float*)d_in[2];
    const float* ln1_b = (const float*)d_in[3];
    const float* wq    = (const float*)d_in[4];
    const float* bq    = (const float*)d_in[5];
    const float* wk    = (const float*)d_in[6];
    const float* bk    = (const float*)d_in[7];
    const float* wv    = (const float*)d_in[8];
    const float* bv    = (const float*)d_in[9];
    const float* wo    = (const float*)d_in[10];
    const float* bo    = (const float*)d_in[11];
    const float* ln2_g = (const float*)d_in[12];
    const float* ln2_b = (const float*)d_in[13];
    const float* w1    = (const float*)d_in[14];
    const float* b1    = (const float*)d_in[15];
    const float* w2    = (const float*)d_in[16];
    const float* b2    = (const float*)d_in[17];
    float* out = (float*)d_out;

    __half *h, *q, *k, *v, *at, *h2, *ff;
    float *x1;
    cudaGetSymbolAddress((void**)&h,  g_h);
    cudaGetSymbolAddress((void**)&q,  g_q);
    cudaGetSymbolAddress((void**)&k,  g_k);
    cudaGetSymbolAddress((void**)&v,  g_v);
    cudaGetSymbolAddress((void**)&at, g_at);
    cudaGetSymbolAddress((void**)&x1, g_x1);
    cudaGetSymbolAddress((void**)&h2, g_h2);
    cudaGetSymbolAddress((void**)&ff, g_ff);
    __half *wqT, *wkT, *wvT, *woT, *w1T, *w2T;
    cudaGetSymbolAddress((void**)&wqT, g_wqT);
    cudaGetSymbolAddress((void**)&wkT, g_wkT);
    cudaGetSymbolAddress((void**)&wvT, g_wvT);
    cudaGetSymbolAddress((void**)&woT, g_woT);
    cudaGetSymbolAddress((void**)&w1T, g_w1T);
    cudaGetSymbolAddress((void**)&w2T, g_w2T);

    const int ATTN_SMEM = (64 * KST + 64 * VST + 64 * SST) * sizeof(float);
    cudaFuncSetAttribute(attn_tc, cudaFuncAttributeMaxDynamicSharedMemorySize, ATTN_SMEM);
    cudaFuncSetAttribute(h_gemm<0, 0>, cudaFuncAttributeMaxDynamicSharedMemorySize, GSM);
    cudaFuncSetAttribute(h_gemm<1, 1>, cudaFuncAttributeMaxDynamicSharedMemorySize, GSM);
    cudaFuncSetAttribute(qkv_gemm, cudaFuncAttributeMaxDynamicSharedMemorySize, GSM);

    // weights: fp32 [K][N] -> fp16 [N][K]
    dim3 tb(32, 8);
    cvt_w<<<dim3(EMB / 32, EMB / 32), tb>>>(wq, wqT, EMB, EMB);
    cvt_w<<<dim3(EMB / 32, EMB / 32), tb>>>(wk, wkT, EMB, EMB);
    cvt_w<<<dim3(EMB / 32, EMB / 32), tb>>>(wv, wvT, EMB, EMB);
    cvt_w<<<dim3(EMB / 32, EMB / 32), tb>>>(wo, woT, EMB, EMB);
    cvt_w<<<dim3(FFD / 32, EMB / 32), tb>>>(w1, w1T, EMB, FFD);
    cvt_w<<<dim3(EMB / 32, FFD / 32), tb>>>(w2, w2T, FFD, EMB);

    ln_kernel<<<TOK, 256>>>(x, ln1_g, ln1_b, h);

    qkv_gemm<<<dim3(24, TOK / 128), 256, GSM>>>(h, bq, bk, bv, q, k, v);

    attn_tc<<<dim3(SEQ / 64, 2 * NHEAD), 128, ATTN_SMEM>>>(q, k, v, at);

    dim3 gE(EMB / 128, TOK / 128);
    h_gemm<0, 0><<<gE, 256, GSM>>>(at, woT, bo, x, x1, TOK, EMB, EMB);

    ln_kernel<<<TOK, 256>>>(x1, ln2_g, ln2_b, h2);

    dim3 gF1(FFD / 128, TOK / 128);
    h_gemm<1, 1><<<gF1, 256, GSM>>>(h2, w1T, b1, nullptr, ff, TOK, FFD, EMB);
    h_gemm<0, 0><<<gE, 256, GSM>>>(ff, w2T, b2, x1, out, TOK, EMB, FFD);
}

// round 9
// speedup vs baseline: 1.9461x; 1.1505x over previous
#include <cuda_runtime.h>
#include <cuda_fp16.h>
#include <math.h>
#include <cstdint>

#define TOK   4096          // B*S
#define SEQ   2048
#define EMB   1024
#define NHEAD 16
#define HDIM  64
#define FFD   4096

// -------- scratch ----
__device__ __half g_h  [TOK * EMB];
__device__ __half g_q  [TOK * EMB];
__device__ __half g_k  [TOK * EMB];
__device__ __half g_v  [TOK * EMB];
__device__ __half g_at [TOK * EMB];
__device__ float  g_x1 [TOK * EMB];
__device__ __half g_h2 [TOK * EMB];
__device__ __half g_ff [TOK * FFD];
// fp16 weights, TRANSPOSED to [N][K]
__device__ __half g_wqT[EMB * EMB];
__device__ __half g_wkT[EMB * EMB];
__device__ __half g_wvT[EMB * EMB];
__device__ __half g_woT[EMB * EMB];
__device__ __half g_w1T[FFD * EMB];
__device__ __half g_w2T[EMB * FFD];

// --------------------------- helpers ------------------------------------------
__device__ __forceinline__ uint32_t smem_u32(const void* p) {
    uint32_t a;
    asm("{ .reg .u64 t; cvta.to.shared.u64 t, %1; cvt.u32.u64 %0, t; }" : "=r"(a) : "l"(p));
    return a;
}
__device__ __forceinline__ uint32_t pack_h2(float lo, float hi) {
    uint32_t r;
    asm("cvt.rn.f16x2.f32 %0, %2, %1;" : "=r"(r) : "f"(lo), "f"(hi));
    return r;
}
__device__ __forceinline__ void cp_async16(uint32_t dst, const void* src) {
    asm volatile("cp.async.cg.shared.global [%0], [%1], 16;" :: "r"(dst), "l"(src));
}
__device__ __forceinline__ void cp_commit() {
    asm volatile("cp.async.commit_group;" ::: "memory");
}
__device__ __forceinline__ void cp_wait2() {
    asm volatile("cp.async.wait_group 2;" ::: "memory");
}
__device__ __forceinline__ void mma_f16(float* d, const uint32_t* a, const uint32_t* b) {
    asm volatile(
        "mma.sync.aligned.m16n8k16.row.col.f32.f16.f16.f32 "
        "{%0,%1,%2,%3},{%4,%5,%6,%7},{%8,%9},{%0,%1,%2,%3};"
        : "+f"(d[0]), "+f"(d[1]), "+f"(d[2]), "+f"(d[3])
        : "r"(a[0]), "r"(a[1]), "r"(a[2]), "r"(a[3]), "r"(b[0]), "r"(b[1]));
}
__device__ __forceinline__ void ldmat4t(uint32_t& r0, uint32_t& r1, uint32_t& r2,
                                        uint32_t& r3, uint32_t addr) {
    asm volatile("ldmatrix.sync.aligned.m8n8.x4.trans.shared.b16 {%0,%1,%2,%3}, [%4];"
                 : "=r"(r0), "=r"(r1), "=r"(r2), "=r"(r3) : "r"(addr));
}

// -------------------- weight convert + transpose (fp32[K][N] -> fp16[N][K]) ---
__global__ void cvt_w(const float* __restrict__ W, __half* __restrict__ WT,
                      int K, int N) {
    __shared__ float tile[32][33];
    int tx = threadIdx.x, ty = threadIdx.y;     // 32 x 8
    int n0 = blockIdx.x * 32, k0 = blockIdx.y * 32;
#pragma unroll
    for (int j = 0; j < 4; j++)
        tile[ty + j * 8][tx] = W[(size_t)(k0 + ty + j * 8) * N + n0 + tx];
    __syncthreads();
#pragma unroll
    for (int j = 0; j < 4; j++)
        WT[(size_t)(n0 + ty + j * 8) * K + k0 + tx] = __float2half(tile[tx][ty + j * 8]);
}

// ------------------------------- LayerNorm (fp16 out) -------------------------
__global__ void ln_kernel(const float* __restrict__ x, const float* __restrict__ g,
                          const float* __restrict__ b, __half* __restrict__ out) {
    int t = blockIdx.x;
    int tid = threadIdx.x;
    const float* row = x + (size_t)t * EMB;
    float vals[4];
    float sum = 0.f, sq = 0.f;
#pragma unroll
    for (int it = 0; it < 4; it++) {
        float v = row[tid + it * 256];
        vals[it] = v; sum += v; sq += v * v;
    }
    __shared__ float s1[256], s2[256];
    s1[tid] = sum; s2[tid] = sq;
    __syncthreads();
    for (int st = 128; st > 0; st >>= 1) {
        if (tid < st) { s1[tid] += s1[tid + st]; s2[tid] += s2[tid + st]; }
        __syncthreads();
    }
    float mu   = s1[0] * (1.f / EMB);
    float var  = s2[0] * (1.f / EMB) - mu * mu;
    float rstd = rsqrtf(var + 1e-5f);
#pragma unroll
    for (int it = 0; it < 4; it++) {
        int i = tid + it * 256;
        out[(size_t)t * EMB + i] = __float2half((vals[it] - mu) * rstd * g[i] + b[i]);
    }
}

// ----------------- fp16 mma GEMM, cp.async 4-stage, BK=32 ---------------------
#define ABY   (128 * 80)
#define BBY   (128 * 80)
#define NSTG  4
#define GSM   (NSTG * (ABY + BBY))

template <int ACT, int OH>
__device__ __forceinline__
void hgemm_core(const __half* __restrict__ A, const __half* __restrict__ WT,
                const float* __restrict__ bias, const float* __restrict__ res,
                void* __restrict__ Cv, int M, int N, int K, int m0, int n0,
                char* smem) {
    uint32_t sbase = smem_u32(smem);
    int tid  = threadIdx.x;
    int lane = tid & 31, warp = tid >> 5;
    int g = lane >> 2, t = lane & 3;
    int wm = (warp >> 2) * 64;
    int wn = (warp & 3) * 32;

    int rrow = tid >> 1;
    int rc   = (tid & 1) * 16;

    const __half* Ap = A  + (size_t)(m0 + rrow) * K + rc;
    const __half* Bp = WT + (size_t)(n0 + rrow) * K + rc;
    uint32_t a_dst0 = sbase + rrow * 80 + rc * 2;
    uint32_t b_dst0 = sbase + NSTG * ABY + rrow * 80 + rc * 2;

    int nkb = K >> 5;

#define ISSUEH(kb, s)                                                          \
    do {                                                                       \
        const __half* asrc = Ap + (size_t)(kb) * 32;                           \
        const __half* bsrc = Bp + (size_t)(kb) * 32;                           \
        uint32_t ad = a_dst0 + (s) * ABY;                                      \
        uint32_t bd = b_dst0 + (s) * BBY;                                      \
        cp_async16(ad,      asrc);      cp_async16(ad + 16, asrc + 8);         \
        cp_async16(bd,      bsrc);      cp_async16(bd + 16, bsrc + 8);         \
    } while (0)

#pragma unroll
    for (int s = 0; s < NSTG - 1; s++) {
        if (s < nkb) ISSUEH(s, s);
        cp_commit();
    }

    float acc[4][4][4] = {};

    for (int kb = 0; kb < nkb; kb++) {
        cp_wait2();
        __syncthreads();

        if (kb + NSTG - 1 < nkb) ISSUEH(kb + NSTG - 1, (kb + NSTG - 1) & (NSTG - 1));
        cp_commit();

        int buf = kb & (NSTG - 1);
        const uint32_t* AsW = (const uint32_t*)(smem + buf * ABY);
        const uint32_t* BsW = (const uint32_t*)(smem + NSTG * ABY + buf * BBY);

#pragma unroll
        for (int ks = 0; ks < 2; ks++) {
            uint32_t a[4][4], b[4][2];
#pragma unroll
            for (int mf = 0; mf < 4; mf++) {
                int r = wm + mf * 16;
                a[mf][0] = AsW[(r + g)     * 20 + ks * 8 + t];
                a[mf][1] = AsW[(r + g + 8) * 20 + ks * 8 + t];
                a[mf][2] = AsW[(r + g)     * 20 + ks * 8 + t + 4];
                a[mf][3] = AsW[(r + g + 8) * 20 + ks * 8 + t + 4];
            }
#pragma unroll
            for (int nf = 0; nf < 4; nf++) {
                int c = wn + nf * 8 + g;
                b[nf][0] = BsW[c * 20 + ks * 8 + t];
                b[nf][1] = BsW[c * 20 + ks * 8 + t + 4];
            }
#pragma unroll
            for (int mf = 0; mf < 4; mf++)
#pragma unroll
                for (int nf = 0; nf < 4; nf++)
                    mma_f16(acc[mf][nf], a[mf], b[nf]);
        }
    }
#undef ISSUEH

#pragma unroll
    for (int mf = 0; mf < 4; mf++) {
#pragma unroll
        for (int nf = 0; nf < 4; nf++) {
            int mA = m0 + wm + mf * 16 + g;
            int mB = mA + 8;
            int n_ = n0 + wn + nf * 8 + 2 * t;
            float bn0 = bias[n_], bn1 = bias[n_ + 1];

            float v00 = acc[mf][nf][0] + bn0;
            float v01 = acc[mf][nf][1] + bn1;
            float v10 = acc[mf][nf][2] + bn0;
            float v11 = acc[mf][nf][3] + bn1;
            if (res) {
                const float2 r0 = *(const float2*)(res + (size_t)mA * N + n_);
                const float2 r1 = *(const float2*)(res + (size_t)mB * N + n_);
                v00 += r0.x; v01 += r0.y; v10 += r1.x; v11 += r1.y;
            }
            if (ACT == 1) {
                v00 = 0.5f * v00 * (1.f + erff(v00 * 0.70710678118654752f));
                v01 = 0.5f * v01 * (1.f + erff(v01 * 0.70710678118654752f));
                v10 = 0.5f * v10 * (1.f + erff(v10 * 0.70710678118654752f));
                v11 = 0.5f * v11 * (1.f + erff(v11 * 0.70710678118654752f));
            }
            if (OH == 1) {
                __half* Ch = (__half*)Cv;
                *(uint32_t*)(Ch + (size_t)mA * N + n_) = pack_h2(v00, v01);
                *(uint32_t*)(Ch + (size_t)mB * N + n_) = pack_h2(v10, v11);
            } else {
                float* Cf = (float*)Cv;
                *(float2*)(Cf + (size_t)mA * N + n_) = make_float2(v00, v01);
                *(float2*)(Cf + (size_t)mB * N + n_) = make_float2(v10, v11);
            }
        }
    }
}

template <int ACT, int OH>
__global__ __launch_bounds__(256, 2)
void h_gemm(const __half* __restrict__ A, const __half* __restrict__ WT,
            const float* __restrict__ bias, const float* __restrict__ res,
            void* __restrict__ C, int M, int N, int K) {
    extern __shared__ char smem[];
    hgemm_core<ACT, OH>(A, WT, bias, res, C, M, N, K,
                        blockIdx.y * 128, blockIdx.x * 128, smem);
}

__global__ __launch_bounds__(256, 2)
void qkv_gemm(const __half* __restrict__ A,
              const float* __restrict__ bq, const float* __restrict__ bk,
              const float* __restrict__ bv,
              __half* __restrict__ Qo, __half* __restrict__ Ko,
              __half* __restrict__ Vo) {
    extern __shared__ char smem[];
    int wsel = blockIdx.x >> 3;
    int n0   = (blockIdx.x & 7) * 128;
    const __half* W;
    const float* bias;
    __half* C;
    if (wsel == 0)      { W = g_wqT; bias = bq; C = Qo; }
    else if (wsel == 1) { W = g_wkT; bias = bk; C = Ko; }
    else                { W = g_wvT; bias = bv; C = Vo; }
    hgemm_core<0, 1>(A, W, bias, nullptr, C, TOK, EMB, EMB,
                     blockIdx.y * 128, n0, smem);
}

// -------------------- fp16 flash attention (m16n8k16) -------------------------
// Block 128 threads (4 warps), 64 Q rows/CTA, warp owns 16 rows.
// Qs/Ks/Vs: [64][72] halves (stride 36 words -> frag banks 4g+t conflict-free).
#define HST 72

__global__ __launch_bounds__(128)
void attn_h(const __half* __restrict__ Q, const __half* __restrict__ K,
            const __half* __restrict__ V, __half* __restrict__ O) {
    extern __shared__ __half smh[];
    __half* Qs = smh;                  // 64*72
    __half* Ks = Qs + 64 * HST;
    __half* Vs = Ks + 64 * HST;
    uint32_t vs_base = smem_u32(Vs);

    int qt = (int)gridDim.x - 1 - (int)blockIdx.x;
    int bh = blockIdx.y;
    int bb = bh >> 4, hh = bh & 15;
    int tid  = threadIdx.x;
    int warp = tid >> 5, lane = tid & 31;
    int g = lane >> 2, t = lane & 3;
    int r0 = warp * 16;

    size_t base = (size_t)bb * SEQ * EMB + (size_t)hh * HDIM;

    // ---- stage Q (scaled by 1/8, exact in fp16) ----
    const __half2 sc8 = __float2half2_rn(0.125f);
#pragma unroll
    for (int it = 0; it < 8; it++) {
        int r = (tid >> 4) + it * 8;
        int c = (tid & 15) * 4;
        const __half2* qp = (const __half2*)(Q + base + (size_t)(qt * 64 + r) * EMB + c);
        __half2 h0 = __hmul2(qp[0], sc8);
        __half2 h1 = __hmul2(qp[1], sc8);
        *(__half2*)&Qs[r * HST + c]     = h0;
        *(__half2*)&Qs[r * HST + c + 2] = h1;
    }
    __syncthreads();

    // Q A-fragments in registers: qa[kc][0..3], kc = k-chunk of 16 dims
    uint32_t qa[4][4];
#pragma unroll
    for (int kc = 0; kc < 4; kc++) {
        qa[kc][0] = *(const uint32_t*)&Qs[(r0 + g)     * HST + kc * 16 + 2 * t];
        qa[kc][1] = *(const uint32_t*)&Qs[(r0 + g + 8) * HST + kc * 16 + 2 * t];
        qa[kc][2] = *(const uint32_t*)&Qs[(r0 + g)     * HST + kc * 16 + 2 * t + 8];
        qa[kc][3] = *(const uint32_t*)&Qs[(r0 + g + 8) * HST + kc * 16 + 2 * t + 8];
    }

    float o[8][4] = {};
    float m0 = -1e30f, m1 = -1e30f, l0 = 0.f, l1 = 0.f;

    // ldmatrix lane address components (per 16x16 V block)
    int lm_key = (lane & 7) + ((lane >> 3) & 1) * 8;   // row within 16-key chunk
    int lm_dim = (lane >> 4) * 8;                      // 0 or 8

    for (int kt = 0; kt <= qt; kt++) {
        // ---- load K, V tiles (fp16, [key][dim], stride 72) ----
#pragma unroll
        for (int it = 0; it < 8; it++) {
            int r = (tid >> 4) + it * 8;
            int c = (tid & 15) * 4;
            size_t go = base + (size_t)(kt * 64 + r) * EMB + c;
            *(uint2*)&Ks[r * HST + c] = *(const uint2*)(K + go);
            *(uint2*)&Vs[r * HST + c] = *(const uint2*)(V + go);
        }
        __syncthreads();

        // ---- S = Q K^T : per nf (8-key group), kc (16-dim chunk) ----
        float s[8][4];
#pragma unroll
        for (int nf = 0; nf < 8; nf++) {
            s[nf][0] = s[nf][1] = s[nf][2] = s[nf][3] = 0.f;
            const __half* kr = &Ks[(nf * 8 + g) * HST];
#pragma unroll
            for (int kc = 0; kc < 4; kc++) {
                uint32_t b[2];
                b[0] = *(const uint32_t*)&kr[kc * 16 + 2 * t];
                b[1] = *(const uint32_t*)&kr[kc * 16 + 2 * t + 8];
                mma_f16(s[nf], qa[kc], b);
            }
        }

        // ---- causal mask on diagonal tile ----
        if (kt == qt) {
            int rowA = r0 + g, rowB = r0 + g + 8;
#pragma unroll
            for (int nf = 0; nf < 8; nf++) {
                int c0 = nf * 8 + 2 * t, c1 = c0 + 1;
                if (c0 > rowA) s[nf][0] = -1e30f;
                if (c1 > rowA) s[nf][1] = -1e30f;
                if (c0 > rowB) s[nf][2] = -1e30f;
                if (c1 > rowB) s[nf][3] = -1e30f;
            }
        }

        // ---- online softmax ----
        float mx0 = -1e30f, mx1 = -1e30f;
#pragma unroll
        for (int nf = 0; nf < 8; nf++) {
            mx0 = fmaxf(mx0, fmaxf(s[nf][0], s[nf][1]));
            mx1 = fmaxf(mx1, fmaxf(s[nf][2], s[nf][3]));
        }
        mx0 = fmaxf(mx0, __shfl_xor_sync(0xffffffffu, mx0, 1));
        mx0 = fmaxf(mx0, __shfl_xor_sync(0xffffffffu, mx0, 2));
        mx1 = fmaxf(mx1, __shfl_xor_sync(0xffffffffu, mx1, 1));
        mx1 = fmaxf(mx1, __shfl_xor_sync(0xffffffffu, mx1, 2));

        float m0n = fmaxf(m0, mx0), m1n = fmaxf(m1, mx1);
        float rs0 = __expf(m0 - m0n), rs1 = __expf(m1 - m1n);
        m0 = m0n; m1 = m1n;

        float sum0 = 0.f, sum1 = 0.f;
#pragma unroll
        for (int nf = 0; nf < 8; nf++) {
            s[nf][0] = __expf(s[nf][0] - m0);
            s[nf][1] = __expf(s[nf][1] - m0);
            s[nf][2] = __expf(s[nf][2] - m1);
            s[nf][3] = __expf(s[nf][3] - m1);
            sum0 += s[nf][0] + s[nf][1];
            sum1 += s[nf][2] + s[nf][3];
        }
        sum0 += __shfl_xor_sync(0xffffffffu, sum0, 1);
        sum0 += __shfl_xor_sync(0xffffffffu, sum0, 2);
        sum1 += __shfl_xor_sync(0xffffffffu, sum1, 1);
        sum1 += __shfl_xor_sync(0xffffffffu, sum1, 2);
        l0 = l0 * rs0 + sum0;
        l1 = l1 * rs1 + sum1;

        // ---- P -> fp16 A-fragments IN REGISTERS (no smem round-trip) ----
        uint32_t pa[4][4];
#pragma unroll
        for (int j = 0; j < 4; j++) {
            pa[j][0] = pack_h2(s[2*j][0],   s[2*j][1]);
            pa[j][1] = pack_h2(s[2*j][2],   s[2*j][3]);
            pa[j][2] = pack_h2(s[2*j+1][0], s[2*j+1][1]);
            pa[j][3] = pack_h2(s[2*j+1][2], s[2*j+1][3]);
        }

        // ---- rescale O, then O += P @ V  (V B-frags via ldmatrix.trans) ----
#pragma unroll
        for (int nf = 0; nf < 8; nf++) {
            o[nf][0] *= rs0; o[nf][1] *= rs0;
            o[nf][2] *= rs1; o[nf][3] *= rs1;
        }
#pragma unroll
        for (int j = 0; j < 4; j++) {
#pragma unroll
            for (int nfp = 0; nfp < 4; nfp++) {
                uint32_t r0v, r1v, r2v, r3v;
                uint32_t addr = vs_base +
                    (uint32_t)(((j * 16 + lm_key) * HST + nfp * 16 + lm_dim) * 2);
                ldmat4t(r0v, r1v, r2v, r3v, addr);
                uint32_t b0[2] = { r0v, r1v };
                uint32_t b1[2] = { r2v, r3v };
                mma_f16(o[2 * nfp],     pa[j], b0);
                mma_f16(o[2 * nfp + 1], pa[j], b1);
            }
        }
        __syncthreads();
    }

    // ---- epilogue ----
    float il0 = 1.f / l0, il1 = 1.f / l1;
    int rowA = qt * 64 + r0 + g;
    int rowB = rowA + 8;
#pragma unroll
    for (int nf = 0; nf < 8; nf++) {
        int c = nf * 8 + 2 * t;
        *(uint32_t*)(O + base + (size_t)rowA * EMB + c) =
            pack_h2(o[nf][0] * il0, o[nf][1] * il0);
        *(uint32_t*)(O + base + (size_t)rowB * EMB + c) =
            pack_h2(o[nf][2] * il1, o[nf][3] * il1);
    }
}

// ------------------------------- launch --------------------------------------
extern "C" void kernel_launch(void* const* d_in, const int* in_sizes, int n_in,
                              void* d_out, int out_size) {
    const float* x     = (const float*)d_in[0];
    const float* ln1_g = (const float*)d_in[2];
    const float* ln1_b = (const float*)d_in[3];
    const float* wq    = (const float*)d_in[4];
    const float* bq    = (const float*)d_in[5];
    const float* wk    = (const float*)d_in[6];
    const float* bk    = (const float*)d_in[7];
    const float* wv    = (const float*)d_in[8];
    const float* bv    = (const float*)d_in[9];
    const float* wo    = (const float*)d_in[10];
    const float* bo    = (const float*)d_in[11];
    const float* ln2_g = (const float*)d_in[12];
    const float* ln2_b = (const float*)d_in[13];
    const float* w1    = (const float*)d_in[14];
    const float* b1    = (const float*)d_in[15];
    const float* w2    = (const float*)d_in[16];
    const float* b2    = (const float*)d_in[17];
    float* out = (float*)d_out;

    __half *h, *q, *k, *v, *at, *h2, *ff;
    float *x1;
    cudaGetSymbolAddress((void**)&h,  g_h);
    cudaGetSymbolAddress((void**)&q,  g_q);
    cudaGetSymbolAddress((void**)&k,  g_k);
    cudaGetSymbolAddress((void**)&v,  g_v);
    cudaGetSymbolAddress((void**)&at, g_at);
    cudaGetSymbolAddress((void**)&x1, g_x1);
    cudaGetSymbolAddress((void**)&h2, g_h2);
    cudaGetSymbolAddress((void**)&ff, g_ff);
    __half *wqT, *wkT, *wvT, *woT, *w1T, *w2T;
    cudaGetSymbolAddress((void**)&wqT, g_wqT);
    cudaGetSymbolAddress((void**)&wkT, g_wkT);
    cudaGetSymbolAddress((void**)&wvT, g_wvT);
    cudaGetSymbolAddress((void**)&woT, g_woT);
    cudaGetSymbolAddress((void**)&w1T, g_w1T);
    cudaGetSymbolAddress((void**)&w2T, g_w2T);

    const int ATTN_SMEM = 3 * 64 * HST * sizeof(__half);   // 27648
    cudaFuncSetAttribute(attn_h, cudaFuncAttributeMaxDynamicSharedMemorySize, ATTN_SMEM);
    cudaFuncSetAttribute(h_gemm<0, 0>, cudaFuncAttributeMaxDynamicSharedMemorySize, GSM);
    cudaFuncSetAttribute(h_gemm<1, 1>, cudaFuncAttributeMaxDynamicSharedMemorySize, GSM);
    cudaFuncSetAttribute(qkv_gemm, cudaFuncAttributeMaxDynamicSharedMemorySize, GSM);

    dim3 tb(32, 8);
    cvt_w<<<dim3(EMB / 32, EMB / 32), tb>>>(wq, wqT, EMB, EMB);
    cvt_w<<<dim3(EMB / 32, EMB / 32), tb>>>(wk, wkT, EMB, EMB);
    cvt_w<<<dim3(EMB / 32, EMB / 32), tb>>>(wv, wvT, EMB, EMB);
    cvt_w<<<dim3(EMB / 32, EMB / 32), tb>>>(wo, woT, EMB, EMB);
    cvt_w<<<dim3(FFD / 32, EMB / 32), tb>>>(w1, w1T, EMB, FFD);
    cvt_w<<<dim3(EMB / 32, FFD / 32), tb>>>(w2, w2T, FFD, EMB);

    ln_kernel<<<TOK, 256>>>(x, ln1_g, ln1_b, h);

    qkv_gemm<<<dim3(24, TOK / 128), 256, GSM>>>(h, bq, bk, bv, q, k, v);

    attn_h<<<dim3(SEQ / 64, 2 * NHEAD), 128, ATTN_SMEM>>>(q, k, v, at);

    dim3 gE(EMB / 128, TOK / 128);
    h_gemm<0, 0><<<gE, 256, GSM>>>(at, woT, bo, x, x1, TOK, EMB, EMB);

    ln_kernel<<<TOK, 256>>>(x1, ln2_g, ln2_b, h2);

    dim3 gF1(FFD / 128, TOK / 128);
    h_gemm<1, 1><<<gF1, 256, GSM>>>(h2, w1T, b1, nullptr, ff, TOK, FFD, EMB);
    h_gemm<0, 0><<<gE, 256, GSM>>>(ff, w2T, b2, x1, out, TOK, EMB, FFD);
}

// round 10
// speedup vs baseline: 2.1368x; 1.0980x over previous
#include <cuda_runtime.h>
#include <cuda_fp16.h>
#include <math.h>
#include <cstdint>

#define TOK   4096          // B*S
#define SEQ   2048
#define EMB   1024
#define NHEAD 16
#define HDIM  64
#define FFD   4096

// -------- scratch ----
__device__ __half g_h  [TOK * EMB];
__device__ __half g_q  [TOK * EMB];
__device__ __half g_k  [TOK * EMB];
__device__ __half g_v  [TOK * EMB];
__device__ __half g_at [TOK * EMB];
__device__ float  g_x1 [TOK * EMB];
__device__ __half g_h2 [TOK * EMB];
__device__ __half g_ff [TOK * FFD];
// fp16 weights, TRANSPOSED to [N][K]
__device__ __half g_wqT[EMB * EMB];
__device__ __half g_wkT[EMB * EMB];
__device__ __half g_wvT[EMB * EMB];
__device__ __half g_woT[EMB * EMB];
__device__ __half g_w1T[FFD * EMB];
__device__ __half g_w2T[EMB * FFD];

// --------------------------- helpers ------------------------------------------
__device__ __forceinline__ uint32_t smem_u32(const void* p) {
    uint32_t a;
    asm("{ .reg .u64 t; cvta.to.shared.u64 t, %1; cvt.u32.u64 %0, t; }" : "=r"(a) : "l"(p));
    return a;
}
__device__ __forceinline__ uint32_t pack_h2(float lo, float hi) {
    uint32_t r;
    asm("cvt.rn.f16x2.f32 %0, %2, %1;" : "=r"(r) : "f"(lo), "f"(hi));
    return r;
}
__device__ __forceinline__ void cp_async16(uint32_t dst, const void* src) {
    asm volatile("cp.async.cg.shared.global [%0], [%1], 16;" :: "r"(dst), "l"(src));
}
__device__ __forceinline__ void cp_commit() {
    asm volatile("cp.async.commit_group;" ::: "memory");
}
__device__ __forceinline__ void cp_wait2() {
    asm volatile("cp.async.wait_group 2;" ::: "memory");
}
__device__ __forceinline__ void mma_f16(float* d, const uint32_t* a, const uint32_t* b) {
    asm volatile(
        "mma.sync.aligned.m16n8k16.row.col.f32.f16.f16.f32 "
        "{%0,%1,%2,%3},{%4,%5,%6,%7},{%8,%9},{%0,%1,%2,%3};"
        : "+f"(d[0]), "+f"(d[1]), "+f"(d[2]), "+f"(d[3])
        : "r"(a[0]), "r"(a[1]), "r"(a[2]), "r"(a[3]), "r"(b[0]), "r"(b[1]));
}
__device__ __forceinline__ void ldmat4(uint32_t& r0, uint32_t& r1, uint32_t& r2,
                                       uint32_t& r3, uint32_t addr) {
    asm volatile("ldmatrix.sync.aligned.m8n8.x4.shared.b16 {%0,%1,%2,%3}, [%4];"
                 : "=r"(r0), "=r"(r1), "=r"(r2), "=r"(r3) : "r"(addr));
}
__device__ __forceinline__ void ldmat4t(uint32_t& r0, uint32_t& r1, uint32_t& r2,
                                        uint32_t& r3, uint32_t addr) {
    asm volatile("ldmatrix.sync.aligned.m8n8.x4.trans.shared.b16 {%0,%1,%2,%3}, [%4];"
                 : "=r"(r0), "=r"(r1), "=r"(r2), "=r"(r3) : "r"(addr));
}

// ---------- combined weight convert + transpose (all 6 in one launch) ---------
// fp32 [K][N] -> fp16 [N][K].  Block = 32x8, 32x32 tile.
__global__ void cvt_all(const float* __restrict__ wq, const float* __restrict__ wk,
                        const float* __restrict__ wv, const float* __restrict__ wo,
                        const float* __restrict__ w1, const float* __restrict__ w2) {
    const int BE = (EMB / 32) * (EMB / 32);      // 1024 blocks per EMBxEMB
    const int BF = (FFD / 32) * (EMB / 32);      // 4096 blocks per FFD matrix
    int bid = blockIdx.x;
    const float* W; __half* WT; int K, N, lb;
    if (bid < BE)            { W = wq; WT = g_wqT; K = EMB; N = EMB; lb = bid; }
    else if (bid < 2 * BE)   { W = wk; WT = g_wkT; K = EMB; N = EMB; lb = bid - BE; }
    else if (bid < 3 * BE)   { W = wv; WT = g_wvT; K = EMB; N = EMB; lb = bid - 2 * BE; }
    else if (bid < 4 * BE)   { W = wo; WT = g_woT; K = EMB; N = EMB; lb = bid - 3 * BE; }
    else if (bid < 4 * BE + BF) { W = w1; WT = g_w1T; K = EMB; N = FFD; lb = bid - 4 * BE; }
    else                     { W = w2; WT = g_w2T; K = FFD; N = EMB; lb = bid - 4 * BE - BF; }

    int nb = N / 32;
    int n0 = (lb % nb) * 32, k0 = (lb / nb) * 32;

    __shared__ float tile[32][33];
    int tx = threadIdx.x, ty = threadIdx.y;
#pragma unroll
    for (int j = 0; j < 4; j++)
        tile[ty + j * 8][tx] = W[(size_t)(k0 + ty + j * 8) * N + n0 + tx];
    __syncthreads();
#pragma unroll
    for (int j = 0; j < 4; j++)
        WT[(size_t)(n0 + ty + j * 8) * K + k0 + tx] = __float2half(tile[tx][ty + j * 8]);
}

// ------------------------------- LayerNorm (fp16 out) -------------------------
__global__ void ln_kernel(const float* __restrict__ x, const float* __restrict__ g,
                          const float* __restrict__ b, __half* __restrict__ out) {
    int t = blockIdx.x;
    int tid = threadIdx.x;
    int lane = tid & 31, w = tid >> 5;
    const float* row = x + (size_t)t * EMB;
    float vals[4];
    float sum = 0.f, sq = 0.f;
#pragma unroll
    for (int it = 0; it < 4; it++) {
        float v = row[tid + it * 256];
        vals[it] = v; sum += v; sq += v * v;
    }
#pragma unroll
    for (int o = 16; o > 0; o >>= 1) {
        sum += __shfl_xor_sync(0xffffffffu, sum, o);
        sq  += __shfl_xor_sync(0xffffffffu, sq, o);
    }
    __shared__ float s1[8], s2[8];
    if (lane == 0) { s1[w] = sum; s2[w] = sq; }
    __syncthreads();
    float tot = 0.f, tq = 0.f;
#pragma unroll
    for (int i = 0; i < 8; i++) { tot += s1[i]; tq += s2[i]; }
    float mu   = tot * (1.f / EMB);
    float var  = tq * (1.f / EMB) - mu * mu;
    float rstd = rsqrtf(var + 1e-5f);
#pragma unroll
    for (int it = 0; it < 4; it++) {
        int i = tid + it * 256;
        out[(size_t)t * EMB + i] = __float2half((vals[it] - mu) * rstd * g[i] + b[i]);
    }
}

// ----------------- fp16 mma GEMM, cp.async 4-stage, BK=32, ldmatrix -----------
#define ABY   (128 * 80)
#define BBY   (128 * 80)
#define NSTG  4
#define GSM   (NSTG * (ABY + BBY))

template <int ACT, int OH>
__device__ __forceinline__
void hgemm_core(const __half* __restrict__ A, const __half* __restrict__ WT,
                const float* __restrict__ bias, const float* __restrict__ res,
                void* __restrict__ Cv, int M, int N, int K, int m0, int n0,
                char* smem) {
    uint32_t sbase = smem_u32(smem);
    int tid  = threadIdx.x;
    int lane = tid & 31, warp = tid >> 5;
    int g = lane >> 2, t = lane & 3;
    int wm = (warp >> 2) * 64;
    int wn = (warp & 3) * 32;

    // ldmatrix lane address components
    int lm_r = ((lane >> 3) & 1) * 8 + (lane & 7);   // row within 16-row block
    int lm_k = (lane >> 4) * 8;                      // half-col 0 or 8

    int rrow = tid >> 1;
    int rc   = (tid & 1) * 16;

    const __half* Ap = A  + (size_t)(m0 + rrow) * K + rc;
    const __half* Bp = WT + (size_t)(n0 + rrow) * K + rc;
    uint32_t a_dst0 = sbase + rrow * 80 + rc * 2;
    uint32_t b_dst0 = sbase + NSTG * ABY + rrow * 80 + rc * 2;

    int nkb = K >> 5;

#define ISSUEH(kb, s)                                                          \
    do {                                                                       \
        const __half* asrc = Ap + (size_t)(kb) * 32;                           \
        const __half* bsrc = Bp + (size_t)(kb) * 32;                           \
        uint32_t ad = a_dst0 + (s) * ABY;                                      \
        uint32_t bd = b_dst0 + (s) * BBY;                                      \
        cp_async16(ad,      asrc);      cp_async16(ad + 16, asrc + 8);         \
        cp_async16(bd,      bsrc);      cp_async16(bd + 16, bsrc + 8);         \
    } while (0)

#pragma unroll
    for (int s = 0; s < NSTG - 1; s++) {
        if (s < nkb) ISSUEH(s, s);
        cp_commit();
    }

    float acc[4][4][4] = {};

    for (int kb = 0; kb < nkb; kb++) {
        cp_wait2();
        __syncthreads();

        if (kb + NSTG - 1 < nkb) ISSUEH(kb + NSTG - 1, (kb + NSTG - 1) & (NSTG - 1));
        cp_commit();

        int buf = kb & (NSTG - 1);
        uint32_t abase = sbase + buf * ABY;
        uint32_t bbase = sbase + NSTG * ABY + buf * BBY;

#pragma unroll
        for (int ks = 0; ks < 2; ks++) {
            uint32_t a[4][4], b[4][2];
#pragma unroll
            for (int mf = 0; mf < 4; mf++) {
                uint32_t addr = abase +
                    (uint32_t)((wm + mf * 16 + lm_r) * 80 + (ks * 16 + lm_k) * 2);
                ldmat4(a[mf][0], a[mf][1], a[mf][2], a[mf][3], addr);
            }
#pragma unroll
            for (int pr = 0; pr < 2; pr++) {
                uint32_t r0, r1, r2, r3;
                uint32_t addr = bbase +
                    (uint32_t)((wn + pr * 16 + lm_r) * 80 + (ks * 16 + lm_k) * 2);
                ldmat4(r0, r1, r2, r3, addr);
                b[2 * pr][0] = r0; b[2 * pr + 1][0] = r1;
                b[2 * pr][1] = r2; b[2 * pr + 1][1] = r3;
            }
#pragma unroll
            for (int mf = 0; mf < 4; mf++)
#pragma unroll
                for (int nf = 0; nf < 4; nf++)
                    mma_f16(acc[mf][nf], a[mf], b[nf]);
        }
    }
#undef ISSUEH

#pragma unroll
    for (int mf = 0; mf < 4; mf++) {
#pragma unroll
        for (int nf = 0; nf < 4; nf++) {
            int mA = m0 + wm + mf * 16 + g;
            int mB = mA + 8;
            int n_ = n0 + wn + nf * 8 + 2 * t;
            float bn0 = bias[n_], bn1 = bias[n_ + 1];

            float v00 = acc[mf][nf][0] + bn0;
            float v01 = acc[mf][nf][1] + bn1;
            float v10 = acc[mf][nf][2] + bn0;
            float v11 = acc[mf][nf][3] + bn1;
            if (res) {
                const float2 r0 = *(const float2*)(res + (size_t)mA * N + n_);
                const float2 r1 = *(const float2*)(res + (size_t)mB * N + n_);
                v00 += r0.x; v01 += r0.y; v10 += r1.x; v11 += r1.y;
            }
            if (ACT == 1) {
                v00 = 0.5f * v00 * (1.f + erff(v00 * 0.70710678118654752f));
                v01 = 0.5f * v01 * (1.f + erff(v01 * 0.70710678118654752f));
                v10 = 0.5f * v10 * (1.f + erff(v10 * 0.70710678118654752f));
                v11 = 0.5f * v11 * (1.f + erff(v11 * 0.70710678118654752f));
            }
            if (OH == 1) {
                __half* Ch = (__half*)Cv;
                *(uint32_t*)(Ch + (size_t)mA * N + n_) = pack_h2(v00, v01);
                *(uint32_t*)(Ch + (size_t)mB * N + n_) = pack_h2(v10, v11);
            } else {
                float* Cf = (float*)Cv;
                *(float2*)(Cf + (size_t)mA * N + n_) = make_float2(v00, v01);
                *(float2*)(Cf + (size_t)mB * N + n_) = make_float2(v10, v11);
            }
        }
    }
}

template <int ACT, int OH>
__global__ __launch_bounds__(256, 2)
void h_gemm(const __half* __restrict__ A, const __half* __restrict__ WT,
            const float* __restrict__ bias, const float* __restrict__ res,
            void* __restrict__ C, int M, int N, int K) {
    extern __shared__ char smem[];
    hgemm_core<ACT, OH>(A, WT, bias, res, C, M, N, K,
                        blockIdx.y * 128, blockIdx.x * 128, smem);
}

__global__ __launch_bounds__(256, 2)
void qkv_gemm(const __half* __restrict__ A,
              const float* __restrict__ bq, const float* __restrict__ bk,
              const float* __restrict__ bv,
              __half* __restrict__ Qo, __half* __restrict__ Ko,
              __half* __restrict__ Vo) {
    extern __shared__ char smem[];
    int wsel = blockIdx.x >> 3;
    int n0   = (blockIdx.x & 7) * 128;
    const __half* W;
    const float* bias;
    __half* C;
    if (wsel == 0)      { W = g_wqT; bias = bq; C = Qo; }
    else if (wsel == 1) { W = g_wkT; bias = bk; C = Ko; }
    else                { W = g_wvT; bias = bv; C = Vo; }
    hgemm_core<0, 1>(A, W, bias, nullptr, C, TOK, EMB, EMB,
                     blockIdx.y * 128, n0, smem);
}

// -------------------- fp16 flash attention (m16n8k16 + ldmatrix) --------------
#define HST 72

__global__ __launch_bounds__(128)
void attn_h(const __half* __restrict__ Q, const __half* __restrict__ K,
            const __half* __restrict__ V, __half* __restrict__ O) {
    extern __shared__ __half smh[];
    __half* Qs = smh;
    __half* Ks = Qs + 64 * HST;
    __half* Vs = Ks + 64 * HST;
    uint32_t ks_base = smem_u32(Ks);
    uint32_t vs_base = smem_u32(Vs);

    int qt = (int)gridDim.x - 1 - (int)blockIdx.x;
    int bh = blockIdx.y;
    int bb = bh >> 4, hh = bh & 15;
    int tid  = threadIdx.x;
    int warp = tid >> 5, lane = tid & 31;
    int g = lane >> 2, t = lane & 3;
    int r0 = warp * 16;

    size_t base = (size_t)bb * SEQ * EMB + (size_t)hh * HDIM;

    const __half2 sc8 = __float2half2_rn(0.125f);
#pragma unroll
    for (int it = 0; it < 8; it++) {
        int r = (tid >> 4) + it * 8;
        int c = (tid & 15) * 4;
        const __half2* qp = (const __half2*)(Q + base + (size_t)(qt * 64 + r) * EMB + c);
        __half2 h0 = __hmul2(qp[0], sc8);
        __half2 h1 = __hmul2(qp[1], sc8);
        *(__half2*)&Qs[r * HST + c]     = h0;
        *(__half2*)&Qs[r * HST + c + 2] = h1;
    }
    __syncthreads();

    uint32_t qa[4][4];
#pragma unroll
    for (int kc = 0; kc < 4; kc++) {
        qa[kc][0] = *(const uint32_t*)&Qs[(r0 + g)     * HST + kc * 16 + 2 * t];
        qa[kc][1] = *(const uint32_t*)&Qs[(r0 + g + 8) * HST + kc * 16 + 2 * t];
        qa[kc][2] = *(const uint32_t*)&Qs[(r0 + g)     * HST + kc * 16 + 2 * t + 8];
        qa[kc][3] = *(const uint32_t*)&Qs[(r0 + g + 8) * HST + kc * 16 + 2 * t + 8];
    }

    float o[8][4] = {};
    float m0 = -1e30f, m1 = -1e30f, l0 = 0.f, l1 = 0.f;

    int lm_r = ((lane >> 3) & 1) * 8 + (lane & 7);
    int lm_k = (lane >> 4) * 8;

    for (int kt = 0; kt <= qt; kt++) {
#pragma unroll
        for (int it = 0; it < 8; it++) {
            int r = (tid >> 4) + it * 8;
            int c = (tid & 15) * 4;
            size_t go = base + (size_t)(kt * 64 + r) * EMB + c;
            *(uint2*)&Ks[r * HST + c] = *(const uint2*)(K + go);
            *(uint2*)&Vs[r * HST + c] = *(const uint2*)(V + go);
        }
        __syncthreads();

        // ---- S = Q K^T via ldmatrix B-frags ----
        float s[8][4] = {};
#pragma unroll
        for (int np = 0; np < 4; np++) {
#pragma unroll
            for (int kc = 0; kc < 4; kc++) {
                uint32_t r0v, r1v, r2v, r3v;
                uint32_t addr = ks_base +
                    (uint32_t)(((np * 16 + lm_r) * HST + kc * 16 + lm_k) * 2);
                ldmat4(r0v, r1v, r2v, r3v, addr);
                uint32_t b0[2] = { r0v, r2v };
                uint32_t b1[2] = { r1v, r3v };
                mma_f16(s[2 * np],     qa[kc], b0);
                mma_f16(s[2 * np + 1], qa[kc], b1);
            }
        }

        if (kt == qt) {
            int rowA = r0 + g, rowB = r0 + g + 8;
#pragma unroll
            for (int nf = 0; nf < 8; nf++) {
                int c0 = nf * 8 + 2 * t, c1 = c0 + 1;
                if (c0 > rowA) s[nf][0] = -1e30f;
                if (c1 > rowA) s[nf][1] = -1e30f;
                if (c0 > rowB) s[nf][2] = -1e30f;
                if (c1 > rowB) s[nf][3] = -1e30f;
            }
        }

        float mx0 = -1e30f, mx1 = -1e30f;
#pragma unroll
        for (int nf = 0; nf < 8; nf++) {
            mx0 = fmaxf(mx0, fmaxf(s[nf][0], s[nf][1]));
            mx1 = fmaxf(mx1, fmaxf(s[nf][2], s[nf][3]));
        }
        mx0 = fmaxf(mx0, __shfl_xor_sync(0xffffffffu, mx0, 1));
        mx0 = fmaxf(mx0, __shfl_xor_sync(0xffffffffu, mx0, 2));
        mx1 = fmaxf(mx1, __shfl_xor_sync(0xffffffffu, mx1, 1));
        mx1 = fmaxf(mx1, __shfl_xor_sync(0xffffffffu, mx1, 2));

        float m0n = fmaxf(m0, mx0), m1n = fmaxf(m1, mx1);
        float rs0 = __expf(m0 - m0n), rs1 = __expf(m1 - m1n);
        m0 = m0n; m1 = m1n;

        float sum0 = 0.f, sum1 = 0.f;
#pragma unroll
        for (int nf = 0; nf < 8; nf++) {
            s[nf][0] = __expf(s[nf][0] - m0);
            s[nf][1] = __expf(s[nf][1] - m0);
            s[nf][2] = __expf(s[nf][2] - m1);
            s[nf][3] = __expf(s[nf][3] - m1);
            sum0 += s[nf][0] + s[nf][1];
            sum1 += s[nf][2] + s[nf][3];
        }
        sum0 += __shfl_xor_sync(0xffffffffu, sum0, 1);
        sum0 += __shfl_xor_sync(0xffffffffu, sum0, 2);
        sum1 += __shfl_xor_sync(0xffffffffu, sum1, 1);
        sum1 += __shfl_xor_sync(0xffffffffu, sum1, 2);
        l0 = l0 * rs0 + sum0;
        l1 = l1 * rs1 + sum1;

        uint32_t pa[4][4];
#pragma unroll
        for (int j = 0; j < 4; j++) {
            pa[j][0] = pack_h2(s[2*j][0],   s[2*j][1]);
            pa[j][1] = pack_h2(s[2*j][2],   s[2*j][3]);
            pa[j][2] = pack_h2(s[2*j+1][0], s[2*j+1][1]);
            pa[j][3] = pack_h2(s[2*j+1][2], s[2*j+1][3]);
        }

#pragma unroll
        for (int nf = 0; nf < 8; nf++) {
            o[nf][0] *= rs0; o[nf][1] *= rs0;
            o[nf][2] *= rs1; o[nf][3] *= rs1;
        }
#pragma unroll
        for (int j = 0; j < 4; j++) {
#pragma unroll
            for (int nfp = 0; nfp < 4; nfp++) {
                uint32_t r0v, r1v, r2v, r3v;
                uint32_t addr = vs_base +
                    (uint32_t)(((j * 16 + lm_r) * HST + nfp * 16 + lm_k) * 2);
                ldmat4t(r0v, r1v, r2v, r3v, addr);
                uint32_t b0[2] = { r0v, r1v };
                uint32_t b1[2] = { r2v, r3v };
                mma_f16(o[2 * nfp],     pa[j], b0);
                mma_f16(o[2 * nfp + 1], pa[j], b1);
            }
        }
        __syncthreads();
    }

    float il0 = 1.f / l0, il1 = 1.f / l1;
    int rowA = qt * 64 + r0 + g;
    int rowB = rowA + 8;
#pragma unroll
    for (int nf = 0; nf < 8; nf++) {
        int c = nf * 8 + 2 * t;
        *(uint32_t*)(O + base + (size_t)rowA * EMB + c) =
            pack_h2(o[nf][0] * il0, o[nf][1] * il0);
        *(uint32_t*)(O + base + (size_t)rowB * EMB + c) =
            pack_h2(o[nf][2] * il1, o[nf][3] * il1);
    }
}

// ------------------------------- launch --------------------------------------
extern "C" void kernel_launch(void* const* d_in, const int* in_sizes, int n_in,
                              void* d_out, int out_size) {
    const float* x     = (const float*)d_in[0];
    const float* ln1_g = (const float*)d_in[2];
    const float* ln1_b = (const float*)d_in[3];
    const float* wq    = (const float*)d_in[4];
    const float* bq    = (const float*)d_in[5];
    const float* wk    = (const float*)d_in[6];
    const float* bk    = (const float*)d_in[7];
    const float* wv    = (const float*)d_in[8];
    const float* bv    = (const float*)d_in[9];
    const float* wo    = (const float*)d_in[10];
    const float* bo    = (const float*)d_in[11];
    const float* ln2_g = (const float*)d_in[12];
    const float* ln2_b = (const float*)d_in[13];
    const float* w1    = (const float*)d_in[14];
    const float* b1    = (const float*)d_in[15];
    const float* w2    = (const float*)d_in[16];
    const float* b2    = (const float*)d_in[17];
    float* out = (float*)d_out;

    __half *h, *q, *k, *v, *at, *h2, *ff;
    float *x1;
    cudaGetSymbolAddress((void**)&h,  g_h);
    cudaGetSymbolAddress((void**)&q,  g_q);
    cudaGetSymbolAddress((void**)&k,  g_k);
    cudaGetSymbolAddress((void**)&v,  g_v);
    cudaGetSymbolAddress((void**)&at, g_at);
    cudaGetSymbolAddress((void**)&x1, g_x1);
    cudaGetSymbolAddress((void**)&h2, g_h2);
    cudaGetSymbolAddress((void**)&ff, g_ff);
    __half *woT, *w1T, *w2T;
    cudaGetSymbolAddress((void**)&woT, g_woT);
    cudaGetSymbolAddress((void**)&w1T, g_w1T);
    cudaGetSymbolAddress((void**)&w2T, g_w2T);

    const int ATTN_SMEM = 3 * 64 * HST * sizeof(__half);
    cudaFuncSetAttribute(attn_h, cudaFuncAttributeMaxDynamicSharedMemorySize, ATTN_SMEM);
    cudaFuncSetAttribute(h_gemm<0, 0>, cudaFuncAttributeMaxDynamicSharedMemorySize, GSM);
    cudaFuncSetAttribute(h_gemm<1, 1>, cudaFuncAttributeMaxDynamicSharedMemorySize, GSM);
    cudaFuncSetAttribute(qkv_gemm, cudaFuncAttributeMaxDynamicSharedMemorySize, GSM);

    // all 6 weight transposes in one launch: 4*1024 + 2*4096 = 12288 blocks
    cvt_all<<<12288, dim3(32, 8)>>>(wq, wk, wv, wo, w1, w2);

    ln_kernel<<<TOK, 256>>>(x, ln1_g, ln1_b, h);

    qkv_gemm<<<dim3(24, TOK / 128), 256, GSM>>>(h, bq, bk, bv, q, k, v);

    attn_h<<<dim3(SEQ / 64, 2 * NHEAD), 128, ATTN_SMEM>>>(q, k, v, at);

    dim3 gE(EMB / 128, TOK / 128);
    h_gemm<0, 0><<<gE, 256, GSM>>>(at, woT, bo, x, x1, TOK, EMB, EMB);

    ln_kernel<<<TOK, 256>>>(x1, ln2_g, ln2_b, h2);

    dim3 gF1(FFD / 128, TOK / 128);
    h_gemm<1, 1><<<gF1, 256, GSM>>>(h2, w1T, b1, nullptr, ff, TOK, FFD, EMB);
    h_gemm<0, 0><<<gE, 256, GSM>>>(ff, w2T, b2, x1, out, TOK, EMB, FFD);
}